// round 6
// baseline (speedup 1.0000x reference)
#include <cuda_runtime.h>
#include <cuda_fp16.h>
#include <math.h>
#include <stdint.h>

// Problem constants
#define BB 8
#define DD 512
#define SS 4096
#define FF 2048

// ---------------- static scratch (no allocations allowed) ----------------
// fp32
__device__ float g_ao[(size_t)BB * SS * DD];
__device__ float g_y [(size_t)BB * SS * DD];
__device__ float g_h2[(size_t)BB * SS * DD];
__device__ double g_acc[32];
// fp16 operands (row-major [x][k] for every GEMM)
__device__ __half g_xh [(size_t)BB * SS * DD];   // x^T  [B,S,D]
__device__ __half g_qh [(size_t)BB * SS * DD];
__device__ __half g_kh [(size_t)BB * SS * DD];
__device__ __half g_vt [(size_t)BB * DD * SS];   // v^T  [B,D,S]
__device__ __half g_sh [(size_t)BB * SS * SS];   // scores/attn fp16
__device__ __half g_t1h[(size_t)BB * SS * DD];
__device__ __half g_yh [(size_t)BB * SS * DD];   // normalized post, fp16 copy
__device__ __half g_h1h[(size_t)BB * SS * FF];
__device__ __half g_wqT[DD * DD];
__device__ __half g_wkT[DD * DD];
__device__ __half g_wvT[DD * DD];
__device__ __half g_woT[DD * DD];
__device__ __half g_w1T[(size_t)DD * FF];        // [F,D]
__device__ __half g_w2T[(size_t)DD * FF];        // [D,F]

// ---------------- helpers ----------------
__device__ __forceinline__ uint32_t smem_u32(const void* p)
{
    uint32_t a;
    asm("{ .reg .u64 t; cvta.to.shared.u64 t, %1; cvt.u32.u64 %0, t; }" : "=r"(a) : "l"(p));
    return a;
}

#define CP16(d, s) asm volatile("cp.async.ca.shared.global [%0], [%1], 16;" :: "r"(d), "l"(s))
#define CPC()  asm volatile("cp.async.commit_group;" ::: "memory")
#define CPW0() asm volatile("cp.async.wait_group 0;" ::: "memory")
#define CPW1() asm volatile("cp.async.wait_group 1;" ::: "memory")

#define LDMX4(r, addr) \
    asm volatile("ldmatrix.sync.aligned.m8n8.x4.shared.b16 {%0,%1,%2,%3}, [%4];" \
        : "=r"((r)[0]), "=r"((r)[1]), "=r"((r)[2]), "=r"((r)[3]) : "r"(addr))

__device__ __forceinline__ void mma16816(float c[4], const uint32_t a[4],
                                         uint32_t b0, uint32_t b1)
{
    asm volatile(
        "mma.sync.aligned.m16n8k16.row.col.f32.f16.f16.f32 "
        "{%0,%1,%2,%3}, {%4,%5,%6,%7}, {%8,%9}, {%0,%1,%2,%3};\n"
        : "+f"(c[0]), "+f"(c[1]), "+f"(c[2]), "+f"(c[3])
        : "r"(a[0]), "r"(a[1]), "r"(a[2]), "r"(a[3]),
          "r"(b0), "r"(b1));
}

// ---------------- fp16 tensor-core GEMM, 3-stage cp.async, ldmatrix ----------------
// C[M,N] = A[M,K] * B[N,K]^T, A/B fp16 row-major. 128x128 tile, TK=64.
// EPI: 0 none, 1 +bias, 2 relu(+bias)
// OUT: 0 fp32 [M,N]; 1 fp16 [M,N]; 2 fp16 transposed [N,M]
#define SKB 144                     // smem row stride in bytes
#define TILE_B (128 * SKB)          // 18432 bytes
#define SMEMB (6 * TILE_B)          // 110592 bytes (3 stages x (A+B))

template <int EPI, int OUT>
__global__ __launch_bounds__(256)
void gemm_h(const __half* __restrict__ A, const __half* __restrict__ B,
            const float* __restrict__ bias, void* __restrict__ Cv,
            int K, int lda, int ldb, int ldc,
            long long sA, long long sB, long long sC)
{
    extern __shared__ char smem[];
    const uint32_t base = smem_u32(smem);

    const int bz = blockIdx.z;
    const __half* Ab = A + (long long)bz * sA;
    const __half* Bb = B + (long long)bz * sB;

    const int m0 = blockIdx.y * 128;
    const int n0 = blockIdx.x * 128;
    const int tid  = threadIdx.x;
    const int lane = tid & 31;
    const int warp = tid >> 5;
    const int wm = (warp >> 2) * 64;
    const int wn = (warp & 3) * 32;
    const int qr = lane >> 2;   // 0..7
    const int qc = lane & 3;    // 0..3

    float acc[4][4][4];
#pragma unroll
    for (int i = 0; i < 4; i++)
#pragma unroll
        for (int j = 0; j < 4; j++)
#pragma unroll
            for (int q = 0; q < 4; q++) acc[i][j][q] = 0.f;

    const int NKB = K >> 6;

    // staging: each operand tile = 128 rows x 128B; 1024 16B chunks, 4/thread
    const int sx = tid >> 3;       // row 0..31 (+32 per iter)
    const int sc = tid & 7;        // 16B chunk in row
    const uint32_t sdst = (uint32_t)(sx * SKB + sc * 16);

#define STAGE(buf, k0)                                                          \
    do {                                                                        \
        const uint32_t aD = base + (buf) * TILE_B + sdst;                       \
        const uint32_t bD = base + (3 + (buf)) * TILE_B + sdst;                 \
        const __half* aSrc = Ab + (long long)(m0 + sx) * lda + (k0) + sc * 8;   \
        const __half* bSrc = Bb + (long long)(n0 + sx) * ldb + (k0) + sc * 8;   \
        _Pragma("unroll")                                                       \
        for (int it = 0; it < 4; it++) {                                        \
            CP16(aD + it * (32 * SKB), aSrc + (long long)(it * 32) * lda);      \
            CP16(bD + it * (32 * SKB), bSrc + (long long)(it * 32) * ldb);      \
        }                                                                       \
    } while (0)

    STAGE(0, 0);
    CPC();
    if (NKB > 1) { STAGE(1, 64); CPC(); }

    // per-lane ldmatrix offsets: lanes 0-15 -> rows (x&15) @ +0B, 16-31 -> @ +16B
    const uint32_t aOff = (uint32_t)((wm + (lane & 15)) * SKB + (lane >> 4) * 16);
    const uint32_t bOff = (uint32_t)((wn + (lane & 15)) * SKB + (lane >> 4) * 16);

    for (int kb = 0; kb < NKB; kb++) {
        if (kb + 1 < NKB) { CPW1(); } else { CPW0(); }
        __syncthreads();
        if (kb + 2 < NKB) { STAGE((kb + 2) % 3, (kb + 2) << 6); CPC(); }

        const int cur = kb % 3;
        const uint32_t aT = base + cur * TILE_B + aOff;
        const uint32_t bT = base + (3 + cur) * TILE_B + bOff;
#pragma unroll
        for (int ks = 0; ks < 4; ks++) {
            uint32_t af[4][4], bq[2][4];
#pragma unroll
            for (int mi = 0; mi < 4; mi++)
                LDMX4(af[mi], aT + mi * (16 * SKB) + ks * 32);
#pragma unroll
            for (int n2 = 0; n2 < 2; n2++)
                LDMX4(bq[n2], bT + n2 * (16 * SKB) + ks * 32);
#pragma unroll
            for (int mi = 0; mi < 4; mi++) {
                mma16816(acc[mi][0], af[mi], bq[0][0], bq[0][2]);
                mma16816(acc[mi][1], af[mi], bq[0][1], bq[0][3]);
                mma16816(acc[mi][2], af[mi], bq[1][0], bq[1][2]);
                mma16816(acc[mi][3], af[mi], bq[1][1], bq[1][3]);
            }
        }
        __syncthreads();
    }
#undef STAGE

    // ---- epilogue ----
#pragma unroll
    for (int mi = 0; mi < 4; mi++) {
        const int m = m0 + wm + mi * 16 + qr;
#pragma unroll
        for (int ni = 0; ni < 4; ni++) {
            const int nc = n0 + wn + ni * 8 + 2 * qc;
            float c0 = acc[mi][ni][0], c1 = acc[mi][ni][1];
            float c2 = acc[mi][ni][2], c3 = acc[mi][ni][3];
            if (EPI >= 1) {
                const float bx = bias[nc], by = bias[nc + 1];
                c0 += bx; c1 += by; c2 += bx; c3 += by;
            }
            if (EPI == 2) {
                c0 = fmaxf(c0, 0.f); c1 = fmaxf(c1, 0.f);
                c2 = fmaxf(c2, 0.f); c3 = fmaxf(c3, 0.f);
            }
            if (OUT == 0) {
                float* C = (float*)Cv + (long long)bz * sC;
                float2 lo; lo.x = c0; lo.y = c1;
                float2 hi; hi.x = c2; hi.y = c3;
                *(float2*)(C + (long long)m * ldc + nc) = lo;
                *(float2*)(C + (long long)(m + 8) * ldc + nc) = hi;
            } else if (OUT == 1) {
                __half* C = (__half*)Cv + (long long)bz * sC;
                *(__half2*)(C + (long long)m * ldc + nc) = __floats2half2_rn(c0, c1);
                *(__half2*)(C + (long long)(m + 8) * ldc + nc) = __floats2half2_rn(c2, c3);
            } else {
                __half* C = (__half*)Cv + (long long)bz * sC;
                C[(long long)nc * ldc + m]           = __float2half_rn(c0);
                C[(long long)(nc + 1) * ldc + m]     = __float2half_rn(c1);
                C[(long long)nc * ldc + m + 8]       = __float2half_rn(c2);
                C[(long long)(nc + 1) * ldc + m + 8] = __float2half_rn(c3);
            }
        }
    }
}

// ---------------- transpose + fp32->fp16 convert: src[R,C] -> dst[C,R] ----------------
__global__ void transpose_h(const float* __restrict__ src, __half* __restrict__ dst,
                            int R, int C)
{
    const int b = blockIdx.z;
    src += (long long)b * R * C;
    dst += (long long)b * R * C;
    const int r0 = blockIdx.y * 32;
    const int c0 = blockIdx.x * 32;
    __shared__ float t[32][33];
    const int tx = threadIdx.x, ty = threadIdx.y;   // 32 x 8
#pragma unroll
    for (int i = 0; i < 32; i += 8)
        t[ty + i][tx] = src[(long long)(r0 + ty + i) * C + c0 + tx];
    __syncthreads();
#pragma unroll
    for (int i = 0; i < 32; i += 8)
        dst[(long long)(c0 + ty + i) * R + r0 + tx] = __float2half_rn(t[tx][ty + i]);
}

// ---------------- softmax on fp16 scores (in place, scaled) ----------------
__global__ void softmax_h(__half* __restrict__ sh, float scale)
{
    const long long row = blockIdx.x;
    uint4* p = (uint4*)(sh + row * SS);       // 512 uint4 per row (8 halves each)
    const int tid = threadIdx.x;              // 256 threads, 2 uint4 each
    __shared__ float red[256];

    uint4 u[2];
    float f[16];
    u[0] = p[tid];
    u[1] = p[tid + 256];
#pragma unroll
    for (int ii = 0; ii < 2; ii++) {
        const uint32_t* w = (const uint32_t*)&u[ii];
#pragma unroll
        for (int j = 0; j < 4; j++) {
            float2 d = __half22float2(*(const __half2*)&w[j]);
            f[ii * 8 + j * 2]     = d.x;
            f[ii * 8 + j * 2 + 1] = d.y;
        }
    }
    float mx = -INFINITY;
#pragma unroll
    for (int i = 0; i < 16; i++) mx = fmaxf(mx, f[i]);
    red[tid] = mx; __syncthreads();
    for (int o = 128; o > 0; o >>= 1) {
        if (tid < o) red[tid] = fmaxf(red[tid], red[tid + o]);
        __syncthreads();
    }
    mx = red[0];
    __syncthreads();

    float sum = 0.f;
#pragma unroll
    for (int i = 0; i < 16; i++) {
        f[i] = __expf((f[i] - mx) * scale);
        sum += f[i];
    }
    red[tid] = sum; __syncthreads();
    for (int o = 128; o > 0; o >>= 1) {
        if (tid < o) red[tid] += red[tid + o];
        __syncthreads();
    }
    const float inv = 1.f / red[0];
#pragma unroll
    for (int ii = 0; ii < 2; ii++) {
        uint32_t* w = (uint32_t*)&u[ii];
#pragma unroll
        for (int j = 0; j < 4; j++) {
            __half2 h = __floats2half2_rn(f[ii * 8 + j * 2] * inv,
                                          f[ii * 8 + j * 2 + 1] * inv);
            w[j] = *(const uint32_t*)&h;
        }
    }
    p[tid]       = u[0];
    p[tid + 256] = u[1];
}

// ---------------- reductions for the global norm ----------------
__device__ __forceinline__ void block_reduce_add2(float a, float b, int t, double* dst)
{
    __shared__ float sa[256], sb[256];
    sa[t] = a; sb[t] = b; __syncthreads();
    for (int o = 128; o > 0; o >>= 1) {
        if (t < o) { sa[t] += sa[t + o]; sb[t] += sb[t + o]; }
        __syncthreads();
    }
    if (t == 0) {
        atomicAdd(dst + 0, (double)sa[0]);
        atomicAdd(dst + 1, (double)sb[0]);
    }
}

__global__ void zero_acc_kernel()
{
    if (threadIdx.x < 32) g_acc[threadIdx.x] = 0.0;
}

// y[b,s,d] = x[b,d,s] + ao[b,s,d]; stats stage 0
__global__ void resid1_kernel(const float* __restrict__ x, const float* __restrict__ ao,
                              float* __restrict__ y)
{
    const int b  = blockIdx.z;
    const int s0 = blockIdx.x * 32;
    const int d0 = blockIdx.y * 32;
    __shared__ float xs[32][33];
    const int tx = threadIdx.x, ty = threadIdx.y;
    const int t = ty * 32 + tx;

    const float* xb = x + (long long)b * DD * SS;
#pragma unroll
    for (int i = 0; i < 32; i += 8)
        xs[ty + i][tx] = xb[(long long)(d0 + ty + i) * SS + s0 + tx];
    __syncthreads();

    float ls = 0.f, lq = 0.f;
#pragma unroll
    for (int i = 0; i < 32; i += 8) {
        long long off = ((long long)b * SS + s0 + ty + i) * DD + d0 + tx;
        float vv = ao[off] + xs[tx][ty + i];
        y[off] = vv;
        ls += vv;
        lq += vv * vv;
    }
    block_reduce_add2(ls, lq, t, g_acc + 2 * b);
}

// normalize y in place (fp32) + write fp16 copy
__global__ void apply1_kernel(float* __restrict__ y, __half* __restrict__ yh)
{
    const int b = blockIdx.y;
    const double sum = g_acc[2 * b], sq = g_acc[2 * b + 1];
    const double NE = (double)SS * DD;
    const double mean = sum / NE;
    double var = sq - NE * mean * mean;
    if (var < 0.0) var = 0.0;
    const float inv = (float)(1.0 / (sqrt(var) + 1e-7));
    const float fm = (float)mean;

    float4* y4 = ((float4*)y) + (long long)b * (SS * DD / 4);
    __half2* yh2 = ((__half2*)yh) + (long long)b * (SS * DD / 2);
    const long long i = (long long)blockIdx.x * 256 + threadIdx.x;  // grid.x = 2048
    float4 vv = y4[i];
    vv.x = (vv.x - fm) * inv; vv.y = (vv.y - fm) * inv;
    vv.z = (vv.z - fm) * inv; vv.w = (vv.w - fm) * inv;
    y4[i] = vv;
    yh2[i * 2]     = __floats2half2_rn(vv.x, vv.y);
    yh2[i * 2 + 1] = __floats2half2_rn(vv.z, vv.w);
}

// h2 <- post + h2 ; stats stage 1
__global__ void resid2_kernel(const float* __restrict__ post, float* __restrict__ h2)
{
    const int b = blockIdx.y;
    const float4* p4 = ((const float4*)post) + (long long)b * (SS * DD / 4);
    float4*       h4 = ((float4*)h2)   + (long long)b * (SS * DD / 4);
    const long long i = (long long)blockIdx.x * 256 + threadIdx.x;
    float4 a = p4[i], cc = h4[i];
    a.x += cc.x; a.y += cc.y; a.z += cc.z; a.w += cc.w;
    h4[i] = a;
    float ls = a.x + a.y + a.z + a.w;
    float lq = a.x * a.x + a.y * a.y + a.z * a.z + a.w * a.w;
    block_reduce_add2(ls, lq, threadIdx.x, g_acc + 16 + 2 * b);
}

// out[b,d,s] = (y2[b,s,d] - mean) * inv
__global__ void apply2t_kernel(const float* __restrict__ y2, float* __restrict__ out)
{
    const int b = blockIdx.z;
    const double sum = g_acc[16 + 2 * b], sq = g_acc[16 + 2 * b + 1];
    const double NE = (double)SS * DD;
    const double mean = sum / NE;
    double var = sq - NE * mean * mean;
    if (var < 0.0) var = 0.0;
    const float inv = (float)(1.0 / (sqrt(var) + 1e-7));
    const float fm = (float)mean;

    const int s0 = blockIdx.x * 32;
    const int d0 = blockIdx.y * 32;
    __shared__ float ys[32][33];
    const int tx = threadIdx.x, ty = threadIdx.y;

#pragma unroll
    for (int i = 0; i < 32; i += 8)
        ys[ty + i][tx] = y2[((long long)b * SS + s0 + ty + i) * DD + d0 + tx];
    __syncthreads();
#pragma unroll
    for (int i = 0; i < 32; i += 8)
        out[((long long)b * DD + d0 + ty + i) * SS + s0 + tx] =
            (ys[tx][ty + i] - fm) * inv;
}

// ---------------- host-side orchestration ----------------
template <typename T>
static T* sym(const void* symbol)
{
    void* p = nullptr;
    cudaGetSymbolAddress(&p, symbol);
    return (T*)p;
}

extern "C" void kernel_launch(void* const* d_in, const int* in_sizes, int n_in,
                              void* d_out, int out_size)
{
    const float* x  = (const float*)d_in[0];
    const float* Wq = (const float*)d_in[1];
    const float* Wk = (const float*)d_in[2];
    const float* Wv = (const float*)d_in[3];
    const float* Wo = (const float*)d_in[4];
    const float* W1 = (const float*)d_in[5];
    const float* b1 = (const float*)d_in[6];
    const float* W2 = (const float*)d_in[7];
    const float* b2 = (const float*)d_in[8];
    float* out = (float*)d_out;

    float*  pao  = sym<float>((const void*)g_ao);
    float*  py   = sym<float>((const void*)g_y);
    float*  ph2  = sym<float>((const void*)g_h2);
    __half* pxh  = sym<__half>((const void*)g_xh);
    __half* pqh  = sym<__half>((const void*)g_qh);
    __half* pkh  = sym<__half>((const void*)g_kh);
    __half* pvt  = sym<__half>((const void*)g_vt);
    __half* psh  = sym<__half>((const void*)g_sh);
    __half* pt1h = sym<__half>((const void*)g_t1h);
    __half* pyh  = sym<__half>((const void*)g_yh);
    __half* ph1h = sym<__half>((const void*)g_h1h);
    __half* pwqT = sym<__half>((const void*)g_wqT);
    __half* pwkT = sym<__half>((const void*)g_wkT);
    __half* pwvT = sym<__half>((const void*)g_wvT);
    __half* pwoT = sym<__half>((const void*)g_woT);
    __half* pw1T = sym<__half>((const void*)g_w1T);
    __half* pw2T = sym<__half>((const void*)g_w2T);

    const long long sSD = (long long)SS * DD;
    const long long sSS = (long long)SS * SS;
    const long long sSF = (long long)SS * FF;
    const long long sDS = (long long)DD * SS;

    cudaFuncSetAttribute(gemm_h<0, 0>, cudaFuncAttributeMaxDynamicSharedMemorySize, SMEMB);
    cudaFuncSetAttribute(gemm_h<0, 1>, cudaFuncAttributeMaxDynamicSharedMemorySize, SMEMB);
    cudaFuncSetAttribute(gemm_h<0, 2>, cudaFuncAttributeMaxDynamicSharedMemorySize, SMEMB);
    cudaFuncSetAttribute(gemm_h<2, 1>, cudaFuncAttributeMaxDynamicSharedMemorySize, SMEMB);
    cudaFuncSetAttribute(gemm_h<1, 0>, cudaFuncAttributeMaxDynamicSharedMemorySize, SMEMB);

    zero_acc_kernel<<<1, 32>>>();

    // pre-pass: fp16 transposed operands
    dim3 tblk(32, 8);
    transpose_h<<<dim3(SS / 32, DD / 32, BB), tblk>>>(x,  pxh,  DD, SS); // x[b]:[D,S]->[S,D]
    transpose_h<<<dim3(DD / 32, DD / 32, 1), tblk>>>(Wq, pwqT, DD, DD);
    transpose_h<<<dim3(DD / 32, DD / 32, 1), tblk>>>(Wk, pwkT, DD, DD);
    transpose_h<<<dim3(DD / 32, DD / 32, 1), tblk>>>(Wv, pwvT, DD, DD);
    transpose_h<<<dim3(DD / 32, DD / 32, 1), tblk>>>(Wo, pwoT, DD, DD);
    transpose_h<<<dim3(FF / 32, DD / 32, 1), tblk>>>(W1, pw1T, DD, FF); // [D,F]->[F,D]
    transpose_h<<<dim3(DD / 32, FF / 32, 1), tblk>>>(W2, pw2T, FF, DD); // [F,D]->[D,F]

    dim3 blk(256);
    dim3 gNarrow(DD / 128, SS / 128, BB);   // (4,32,8)
    dim3 gScore(SS / 128, SS / 128, BB);    // (32,32,8)
    dim3 gFFN(FF / 128, SS / 128, BB);      // (16,32,8)

    // q,k = xh @ WT  (fp16 out)
    gemm_h<0, 1><<<gNarrow, blk, SMEMB>>>(pxh, pwqT, nullptr, pqh,
        DD, DD, DD, DD, sSD, 0, sSD);
    gemm_h<0, 1><<<gNarrow, blk, SMEMB>>>(pxh, pwkT, nullptr, pkh,
        DD, DD, DD, DD, sSD, 0, sSD);
    // v = xh @ WvT (fp16 out, transposed to [D,S])
    gemm_h<0, 2><<<gNarrow, blk, SMEMB>>>(pxh, pwvT, nullptr, pvt,
        DD, DD, DD, SS, sSD, 0, sDS);

    // scores = q @ k^T (fp16 out, in place softmax next)
    gemm_h<0, 1><<<gScore, blk, SMEMB>>>(pqh, pkh, nullptr, psh,
        DD, DD, DD, SS, sSD, sSD, sSS);

    softmax_h<<<BB * SS, 256>>>(psh, 0.04419417382415922f /* 1/sqrt(512) */);

    // t1 = attn @ v  (A=[S,S], B=vT[D,S]; fp16 out)
    gemm_h<0, 1><<<gNarrow, blk, SMEMB>>>(psh, pvt, nullptr, pt1h,
        SS, SS, SS, DD, sSS, sDS, sSD);

    // ao = t1 @ Wo (fp32 out)
    gemm_h<0, 0><<<gNarrow, blk, SMEMB>>>(pt1h, pwoT, nullptr, pao,
        DD, DD, DD, DD, sSD, 0, sSD);

    dim3 rgrid(SS / 32, DD / 32, BB);
    resid1_kernel<<<rgrid, tblk>>>(x, pao, py);
    apply1_kernel<<<dim3(2048, BB), 256>>>(py, pyh);

    // FFN
    gemm_h<2, 1><<<gFFN, blk, SMEMB>>>(pyh, pw1T, b1, ph1h,
        DD, DD, DD, FF, sSD, 0, sSF);
    gemm_h<1, 0><<<gNarrow, blk, SMEMB>>>(ph1h, pw2T, b2, ph2,
        FF, FF, FF, DD, sSF, 0, sSD);

    resid2_kernel<<<dim3(2048, BB), 256>>>(py, ph2);
    apply2t_kernel<<<rgrid, tblk>>>(ph2, out);

    (void)in_sizes; (void)n_in; (void)out_size;
}

// round 7
// speedup vs baseline: 1.1677x; 1.1677x over previous
#include <cuda_runtime.h>
#include <cuda_fp16.h>
#include <math.h>
#include <stdint.h>

// Problem constants
#define BB 8
#define DD 512
#define SS 4096
#define FF 2048

// ---------------- static scratch (no allocations allowed) ----------------
// fp32
__device__ float g_ao[(size_t)BB * SS * DD];
__device__ float g_y [(size_t)BB * SS * DD];
__device__ float g_h2[(size_t)BB * SS * DD];
__device__ double g_acc[32];
// fp16 operands (row-major [x][k] for every GEMM)
__device__ __half g_xh [(size_t)BB * SS * DD];   // x^T  [B,S,D]
__device__ __half g_qh [(size_t)BB * SS * DD];
__device__ __half g_kh [(size_t)BB * SS * DD];
__device__ __half g_vt [(size_t)BB * DD * SS];   // v^T  [B,D,S]
__device__ __half g_sh [(size_t)BB * SS * SS];   // scores/attn fp16
__device__ __half g_t1h[(size_t)BB * SS * DD];
__device__ __half g_yh [(size_t)BB * SS * DD];   // normalized post, fp16 copy
__device__ __half g_h1h[(size_t)BB * SS * FF];
__device__ __half g_wqT[DD * DD];
__device__ __half g_wkT[DD * DD];
__device__ __half g_wvT[DD * DD];
__device__ __half g_woT[DD * DD];
__device__ __half g_w1T[(size_t)DD * FF];        // [F,D]
__device__ __half g_w2T[(size_t)DD * FF];        // [D,F]

// ---------------- helpers ----------------
__device__ __forceinline__ uint32_t smem_u32(const void* p)
{
    uint32_t a;
    asm("{ .reg .u64 t; cvta.to.shared.u64 t, %1; cvt.u32.u64 %0, t; }" : "=r"(a) : "l"(p));
    return a;
}

#define CP16(d, s) asm volatile("cp.async.ca.shared.global [%0], [%1], 16;" :: "r"(d), "l"(s))
#define CPC()  asm volatile("cp.async.commit_group;" ::: "memory")
#define CPW0() asm volatile("cp.async.wait_group 0;" ::: "memory")
#define CPW1() asm volatile("cp.async.wait_group 1;" ::: "memory")

#define LDMX4(r, addr) \
    asm volatile("ldmatrix.sync.aligned.m8n8.x4.shared.b16 {%0,%1,%2,%3}, [%4];" \
        : "=r"((r)[0]), "=r"((r)[1]), "=r"((r)[2]), "=r"((r)[3]) : "r"(addr))

__device__ __forceinline__ void mma16816(float c[4], const uint32_t a[4],
                                         uint32_t b0, uint32_t b1)
{
    asm volatile(
        "mma.sync.aligned.m16n8k16.row.col.f32.f16.f16.f32 "
        "{%0,%1,%2,%3}, {%4,%5,%6,%7}, {%8,%9}, {%0,%1,%2,%3};\n"
        : "+f"(c[0]), "+f"(c[1]), "+f"(c[2]), "+f"(c[3])
        : "r"(a[0]), "r"(a[1]), "r"(a[2]), "r"(a[3]),
          "r"(b0), "r"(b1));
}

// ---------------- fp16 tensor-core GEMM, 2-stage cp.async + ldmatrix ----------------
// C[M,N] = A[M,K] * B[N,K]^T, A/B fp16 row-major. 128x128 tile, TK=64.
// EPI: 0 none, 1 +bias, 2 relu(+bias)
// OUT: 0 fp32 [M,N]; 1 fp16 [M,N]; 2 fp16 transposed [N,M]
#define SKB 144                     // smem row stride in bytes
#define TILE_B (128 * SKB)          // 18432 bytes
#define SMEMB (4 * TILE_B)          // 73728 bytes (2 stages x (A+B)) -> 2 CTAs/SM

template <int EPI, int OUT>
__global__ __launch_bounds__(256)
void gemm_h(const __half* __restrict__ A, const __half* __restrict__ B,
            const float* __restrict__ bias, void* __restrict__ Cv,
            int K, int lda, int ldb, int ldc,
            long long sA, long long sB, long long sC)
{
    extern __shared__ char smem[];
    const uint32_t base = smem_u32(smem);

    const int bz = blockIdx.z;
    const __half* Ab = A + (long long)bz * sA;
    const __half* Bb = B + (long long)bz * sB;

    const int m0 = blockIdx.y * 128;
    const int n0 = blockIdx.x * 128;
    const int tid  = threadIdx.x;
    const int lane = tid & 31;
    const int warp = tid >> 5;
    const int wm = (warp >> 2) * 64;
    const int wn = (warp & 3) * 32;
    const int qr = lane >> 2;   // 0..7
    const int qc = lane & 3;    // 0..3

    float acc[4][4][4];
#pragma unroll
    for (int i = 0; i < 4; i++)
#pragma unroll
        for (int j = 0; j < 4; j++)
#pragma unroll
            for (int q = 0; q < 4; q++) acc[i][j][q] = 0.f;

    const int NKB = K >> 6;

    // staging: each operand tile = 128 rows x 128B; 1024 16B chunks, 4/thread
    const int sx = tid >> 3;       // row 0..31 (+32 per iter)
    const int sc = tid & 7;        // 16B chunk in row
    const uint32_t sdst = (uint32_t)(sx * SKB + sc * 16);

#define STAGE(buf, k0)                                                          \
    do {                                                                        \
        const uint32_t aD = base + (buf) * TILE_B + sdst;                       \
        const uint32_t bD = base + (2 + (buf)) * TILE_B + sdst;                 \
        const __half* aSrc = Ab + (long long)(m0 + sx) * lda + (k0) + sc * 8;   \
        const __half* bSrc = Bb + (long long)(n0 + sx) * ldb + (k0) + sc * 8;   \
        _Pragma("unroll")                                                       \
        for (int it = 0; it < 4; it++) {                                        \
            CP16(aD + it * (32 * SKB), aSrc + (long long)(it * 32) * lda);      \
            CP16(bD + it * (32 * SKB), bSrc + (long long)(it * 32) * ldb);      \
        }                                                                       \
    } while (0)

    STAGE(0, 0);
    CPC();

    // per-lane ldmatrix offsets: lanes 0-15 -> rows (x&15) @ +0B, 16-31 -> @ +16B
    const uint32_t aOff = (uint32_t)((wm + (lane & 15)) * SKB + (lane >> 4) * 16);
    const uint32_t bOff = (uint32_t)((wn + (lane & 15)) * SKB + (lane >> 4) * 16);

    for (int kb = 0; kb < NKB; kb++) {
        const int cur = kb & 1;
        if (kb + 1 < NKB) {
            STAGE(cur ^ 1, (kb + 1) << 6);
            CPC();
            CPW1();
        } else {
            CPW0();
        }
        __syncthreads();

        const uint32_t aT = base + cur * TILE_B + aOff;
        const uint32_t bT = base + (2 + cur) * TILE_B + bOff;
#pragma unroll
        for (int ks = 0; ks < 4; ks++) {
            uint32_t af[4][4], bq[2][4];
#pragma unroll
            for (int mi = 0; mi < 4; mi++)
                LDMX4(af[mi], aT + mi * (16 * SKB) + ks * 32);
#pragma unroll
            for (int n2 = 0; n2 < 2; n2++)
                LDMX4(bq[n2], bT + n2 * (16 * SKB) + ks * 32);
#pragma unroll
            for (int mi = 0; mi < 4; mi++) {
                mma16816(acc[mi][0], af[mi], bq[0][0], bq[0][2]);
                mma16816(acc[mi][1], af[mi], bq[0][1], bq[0][3]);
                mma16816(acc[mi][2], af[mi], bq[1][0], bq[1][2]);
                mma16816(acc[mi][3], af[mi], bq[1][1], bq[1][3]);
            }
        }
        __syncthreads();
    }
#undef STAGE

    // ---- epilogue ----
#pragma unroll
    for (int mi = 0; mi < 4; mi++) {
        const int m = m0 + wm + mi * 16 + qr;
#pragma unroll
        for (int ni = 0; ni < 4; ni++) {
            const int nc = n0 + wn + ni * 8 + 2 * qc;
            float c0 = acc[mi][ni][0], c1 = acc[mi][ni][1];
            float c2 = acc[mi][ni][2], c3 = acc[mi][ni][3];
            if (EPI >= 1) {
                const float bx = bias[nc], by = bias[nc + 1];
                c0 += bx; c1 += by; c2 += bx; c3 += by;
            }
            if (EPI == 2) {
                c0 = fmaxf(c0, 0.f); c1 = fmaxf(c1, 0.f);
                c2 = fmaxf(c2, 0.f); c3 = fmaxf(c3, 0.f);
            }
            if (OUT == 0) {
                float* C = (float*)Cv + (long long)bz * sC;
                float2 lo; lo.x = c0; lo.y = c1;
                float2 hi; hi.x = c2; hi.y = c3;
                *(float2*)(C + (long long)m * ldc + nc) = lo;
                *(float2*)(C + (long long)(m + 8) * ldc + nc) = hi;
            } else if (OUT == 1) {
                __half* C = (__half*)Cv + (long long)bz * sC;
                *(__half2*)(C + (long long)m * ldc + nc) = __floats2half2_rn(c0, c1);
                *(__half2*)(C + (long long)(m + 8) * ldc + nc) = __floats2half2_rn(c2, c3);
            } else {
                __half* C = (__half*)Cv + (long long)bz * sC;
                C[(long long)nc * ldc + m]           = __float2half_rn(c0);
                C[(long long)(nc + 1) * ldc + m]     = __float2half_rn(c1);
                C[(long long)nc * ldc + m + 8]       = __float2half_rn(c2);
                C[(long long)(nc + 1) * ldc + m + 8] = __float2half_rn(c3);
            }
        }
    }
}

// ---------------- transpose + fp32->fp16 convert: src[R,C] -> dst[C,R] ----------------
__global__ void transpose_h(const float* __restrict__ src, __half* __restrict__ dst,
                            int R, int C)
{
    const int b = blockIdx.z;
    src += (long long)b * R * C;
    dst += (long long)b * R * C;
    const int r0 = blockIdx.y * 32;
    const int c0 = blockIdx.x * 32;
    __shared__ float t[32][33];
    const int tx = threadIdx.x, ty = threadIdx.y;   // 32 x 8
#pragma unroll
    for (int i = 0; i < 32; i += 8)
        t[ty + i][tx] = src[(long long)(r0 + ty + i) * C + c0 + tx];
    __syncthreads();
#pragma unroll
    for (int i = 0; i < 32; i += 8)
        dst[(long long)(c0 + ty + i) * R + r0 + tx] = __float2half_rn(t[tx][ty + i]);
}

// ---------------- softmax on fp16 scores (in place, scaled) ----------------
__global__ void softmax_h(__half* __restrict__ sh, float scale)
{
    const long long row = blockIdx.x;
    uint4* p = (uint4*)(sh + row * SS);       // 512 uint4 per row (8 halves each)
    const int tid = threadIdx.x;              // 256 threads, 2 uint4 each
    __shared__ float red[256];

    uint4 u[2];
    float f[16];
    u[0] = p[tid];
    u[1] = p[tid + 256];
#pragma unroll
    for (int ii = 0; ii < 2; ii++) {
        const uint32_t* w = (const uint32_t*)&u[ii];
#pragma unroll
        for (int j = 0; j < 4; j++) {
            float2 d = __half22float2(*(const __half2*)&w[j]);
            f[ii * 8 + j * 2]     = d.x;
            f[ii * 8 + j * 2 + 1] = d.y;
        }
    }
    float mx = -INFINITY;
#pragma unroll
    for (int i = 0; i < 16; i++) mx = fmaxf(mx, f[i]);
    red[tid] = mx; __syncthreads();
    for (int o = 128; o > 0; o >>= 1) {
        if (tid < o) red[tid] = fmaxf(red[tid], red[tid + o]);
        __syncthreads();
    }
    mx = red[0];
    __syncthreads();

    float sum = 0.f;
#pragma unroll
    for (int i = 0; i < 16; i++) {
        f[i] = __expf((f[i] - mx) * scale);
        sum += f[i];
    }
    red[tid] = sum; __syncthreads();
    for (int o = 128; o > 0; o >>= 1) {
        if (tid < o) red[tid] += red[tid + o];
        __syncthreads();
    }
    const float inv = 1.f / red[0];
#pragma unroll
    for (int ii = 0; ii < 2; ii++) {
        uint32_t* w = (uint32_t*)&u[ii];
#pragma unroll
        for (int j = 0; j < 4; j++) {
            __half2 h = __floats2half2_rn(f[ii * 8 + j * 2] * inv,
                                          f[ii * 8 + j * 2 + 1] * inv);
            w[j] = *(const uint32_t*)&h;
        }
    }
    p[tid]       = u[0];
    p[tid + 256] = u[1];
}

// ---------------- reductions for the global norm ----------------
__device__ __forceinline__ void block_reduce_add2(float a, float b, int t, double* dst)
{
    __shared__ float sa[256], sb[256];
    sa[t] = a; sb[t] = b; __syncthreads();
    for (int o = 128; o > 0; o >>= 1) {
        if (t < o) { sa[t] += sa[t + o]; sb[t] += sb[t + o]; }
        __syncthreads();
    }
    if (t == 0) {
        atomicAdd(dst + 0, (double)sa[0]);
        atomicAdd(dst + 1, (double)sb[0]);
    }
}

__global__ void zero_acc_kernel()
{
    if (threadIdx.x < 32) g_acc[threadIdx.x] = 0.0;
}

// y[b,s,d] = x[b,d,s] + ao[b,s,d]; stats stage 0
__global__ void resid1_kernel(const float* __restrict__ x, const float* __restrict__ ao,
                              float* __restrict__ y)
{
    const int b  = blockIdx.z;
    const int s0 = blockIdx.x * 32;
    const int d0 = blockIdx.y * 32;
    __shared__ float xs[32][33];
    const int tx = threadIdx.x, ty = threadIdx.y;
    const int t = ty * 32 + tx;

    const float* xb = x + (long long)b * DD * SS;
#pragma unroll
    for (int i = 0; i < 32; i += 8)
        xs[ty + i][tx] = xb[(long long)(d0 + ty + i) * SS + s0 + tx];
    __syncthreads();

    float ls = 0.f, lq = 0.f;
#pragma unroll
    for (int i = 0; i < 32; i += 8) {
        long long off = ((long long)b * SS + s0 + ty + i) * DD + d0 + tx;
        float vv = ao[off] + xs[tx][ty + i];
        y[off] = vv;
        ls += vv;
        lq += vv * vv;
    }
    block_reduce_add2(ls, lq, t, g_acc + 2 * b);
}

// normalize y in place (fp32) + write fp16 copy
__global__ void apply1_kernel(float* __restrict__ y, __half* __restrict__ yh)
{
    const int b = blockIdx.y;
    const double sum = g_acc[2 * b], sq = g_acc[2 * b + 1];
    const double NE = (double)SS * DD;
    const double mean = sum / NE;
    double var = sq - NE * mean * mean;
    if (var < 0.0) var = 0.0;
    const float inv = (float)(1.0 / (sqrt(var) + 1e-7));
    const float fm = (float)mean;

    float4* y4 = ((float4*)y) + (long long)b * (SS * DD / 4);
    __half2* yh2 = ((__half2*)yh) + (long long)b * (SS * DD / 2);
    const long long i = (long long)blockIdx.x * 256 + threadIdx.x;  // grid.x = 2048
    float4 vv = y4[i];
    vv.x = (vv.x - fm) * inv; vv.y = (vv.y - fm) * inv;
    vv.z = (vv.z - fm) * inv; vv.w = (vv.w - fm) * inv;
    y4[i] = vv;
    yh2[i * 2]     = __floats2half2_rn(vv.x, vv.y);
    yh2[i * 2 + 1] = __floats2half2_rn(vv.z, vv.w);
}

// h2 <- post + h2 ; stats stage 1
__global__ void resid2_kernel(const float* __restrict__ post, float* __restrict__ h2)
{
    const int b = blockIdx.y;
    const float4* p4 = ((const float4*)post) + (long long)b * (SS * DD / 4);
    float4*       h4 = ((float4*)h2)   + (long long)b * (SS * DD / 4);
    const long long i = (long long)blockIdx.x * 256 + threadIdx.x;
    float4 a = p4[i], cc = h4[i];
    a.x += cc.x; a.y += cc.y; a.z += cc.z; a.w += cc.w;
    h4[i] = a;
    float ls = a.x + a.y + a.z + a.w;
    float lq = a.x * a.x + a.y * a.y + a.z * a.z + a.w * a.w;
    block_reduce_add2(ls, lq, threadIdx.x, g_acc + 16 + 2 * b);
}

// out[b,d,s] = (y2[b,s,d] - mean) * inv
__global__ void apply2t_kernel(const float* __restrict__ y2, float* __restrict__ out)
{
    const int b = blockIdx.z;
    const double sum = g_acc[16 + 2 * b], sq = g_acc[16 + 2 * b + 1];
    const double NE = (double)SS * DD;
    const double mean = sum / NE;
    double var = sq - NE * mean * mean;
    if (var < 0.0) var = 0.0;
    const float inv = (float)(1.0 / (sqrt(var) + 1e-7));
    const float fm = (float)mean;

    const int s0 = blockIdx.x * 32;
    const int d0 = blockIdx.y * 32;
    __shared__ float ys[32][33];
    const int tx = threadIdx.x, ty = threadIdx.y;

#pragma unroll
    for (int i = 0; i < 32; i += 8)
        ys[ty + i][tx] = y2[((long long)b * SS + s0 + ty + i) * DD + d0 + tx];
    __syncthreads();
#pragma unroll
    for (int i = 0; i < 32; i += 8)
        out[((long long)b * DD + d0 + ty + i) * SS + s0 + tx] =
            (ys[tx][ty + i] - fm) * inv;
}

// ---------------- host-side orchestration ----------------
template <typename T>
static T* sym(const void* symbol)
{
    void* p = nullptr;
    cudaGetSymbolAddress(&p, symbol);
    return (T*)p;
}

extern "C" void kernel_launch(void* const* d_in, const int* in_sizes, int n_in,
                              void* d_out, int out_size)
{
    const float* x  = (const float*)d_in[0];
    const float* Wq = (const float*)d_in[1];
    const float* Wk = (const float*)d_in[2];
    const float* Wv = (const float*)d_in[3];
    const float* Wo = (const float*)d_in[4];
    const float* W1 = (const float*)d_in[5];
    const float* b1 = (const float*)d_in[6];
    const float* W2 = (const float*)d_in[7];
    const float* b2 = (const float*)d_in[8];
    float* out = (float*)d_out;

    float*  pao  = sym<float>((const void*)g_ao);
    float*  py   = sym<float>((const void*)g_y);
    float*  ph2  = sym<float>((const void*)g_h2);
    __half* pxh  = sym<__half>((const void*)g_xh);
    __half* pqh  = sym<__half>((const void*)g_qh);
    __half* pkh  = sym<__half>((const void*)g_kh);
    __half* pvt  = sym<__half>((const void*)g_vt);
    __half* psh  = sym<__half>((const void*)g_sh);
    __half* pt1h = sym<__half>((const void*)g_t1h);
    __half* pyh  = sym<__half>((const void*)g_yh);
    __half* ph1h = sym<__half>((const void*)g_h1h);
    __half* pwqT = sym<__half>((const void*)g_wqT);
    __half* pwkT = sym<__half>((const void*)g_wkT);
    __half* pwvT = sym<__half>((const void*)g_wvT);
    __half* pwoT = sym<__half>((const void*)g_woT);
    __half* pw1T = sym<__half>((const void*)g_w1T);
    __half* pw2T = sym<__half>((const void*)g_w2T);

    const long long sSD = (long long)SS * DD;
    const long long sSS = (long long)SS * SS;
    const long long sSF = (long long)SS * FF;
    const long long sDS = (long long)DD * SS;

    cudaFuncSetAttribute(gemm_h<0, 0>, cudaFuncAttributeMaxDynamicSharedMemorySize, SMEMB);
    cudaFuncSetAttribute(gemm_h<0, 1>, cudaFuncAttributeMaxDynamicSharedMemorySize, SMEMB);
    cudaFuncSetAttribute(gemm_h<0, 2>, cudaFuncAttributeMaxDynamicSharedMemorySize, SMEMB);
    cudaFuncSetAttribute(gemm_h<2, 1>, cudaFuncAttributeMaxDynamicSharedMemorySize, SMEMB);
    cudaFuncSetAttribute(gemm_h<1, 0>, cudaFuncAttributeMaxDynamicSharedMemorySize, SMEMB);

    zero_acc_kernel<<<1, 32>>>();

    // pre-pass: fp16 transposed operands
    dim3 tblk(32, 8);
    transpose_h<<<dim3(SS / 32, DD / 32, BB), tblk>>>(x,  pxh,  DD, SS); // x[b]:[D,S]->[S,D]
    transpose_h<<<dim3(DD / 32, DD / 32, 1), tblk>>>(Wq, pwqT, DD, DD);
    transpose_h<<<dim3(DD / 32, DD / 32, 1), tblk>>>(Wk, pwkT, DD, DD);
    transpose_h<<<dim3(DD / 32, DD / 32, 1), tblk>>>(Wv, pwvT, DD, DD);
    transpose_h<<<dim3(DD / 32, DD / 32, 1), tblk>>>(Wo, pwoT, DD, DD);
    transpose_h<<<dim3(FF / 32, DD / 32, 1), tblk>>>(W1, pw1T, DD, FF); // [D,F]->[F,D]
    transpose_h<<<dim3(DD / 32, FF / 32, 1), tblk>>>(W2, pw2T, FF, DD); // [F,D]->[D,F]

    dim3 blk(256);
    dim3 gNarrow(DD / 128, SS / 128, BB);   // (4,32,8)
    dim3 gScore(SS / 128, SS / 128, BB);    // (32,32,8)
    dim3 gFFN(FF / 128, SS / 128, BB);      // (16,32,8)

    // q,k = xh @ WT  (fp16 out)
    gemm_h<0, 1><<<gNarrow, blk, SMEMB>>>(pxh, pwqT, nullptr, pqh,
        DD, DD, DD, DD, sSD, 0, sSD);
    gemm_h<0, 1><<<gNarrow, blk, SMEMB>>>(pxh, pwkT, nullptr, pkh,
        DD, DD, DD, DD, sSD, 0, sSD);
    // v = xh @ WvT (fp16 out, transposed to [D,S])
    gemm_h<0, 2><<<gNarrow, blk, SMEMB>>>(pxh, pwvT, nullptr, pvt,
        DD, DD, DD, SS, sSD, 0, sDS);

    // scores = q @ k^T (fp16 out, in place softmax next)
    gemm_h<0, 1><<<gScore, blk, SMEMB>>>(pqh, pkh, nullptr, psh,
        DD, DD, DD, SS, sSD, sSD, sSS);

    softmax_h<<<BB * SS, 256>>>(psh, 0.04419417382415922f /* 1/sqrt(512) */);

    // t1 = attn @ v  (A=[S,S], B=vT[D,S]; fp16 out)
    gemm_h<0, 1><<<gNarrow, blk, SMEMB>>>(psh, pvt, nullptr, pt1h,
        SS, SS, SS, DD, sSS, sDS, sSD);

    // ao = t1 @ Wo (fp32 out)
    gemm_h<0, 0><<<gNarrow, blk, SMEMB>>>(pt1h, pwoT, nullptr, pao,
        DD, DD, DD, DD, sSD, 0, sSD);

    dim3 rgrid(SS / 32, DD / 32, BB);
    resid1_kernel<<<rgrid, tblk>>>(x, pao, py);
    apply1_kernel<<<dim3(2048, BB), 256>>>(py, pyh);

    // FFN
    gemm_h<2, 1><<<gFFN, blk, SMEMB>>>(pyh, pw1T, b1, ph1h,
        DD, DD, DD, FF, sSD, 0, sSF);
    gemm_h<1, 0><<<gNarrow, blk, SMEMB>>>(ph1h, pw2T, b2, ph2,
        FF, FF, FF, DD, sSF, 0, sSD);

    resid2_kernel<<<dim3(2048, BB), 256>>>(py, ph2);
    apply2t_kernel<<<rgrid, tblk>>>(ph2, out);

    (void)in_sizes; (void)n_in; (void)out_size;
}

// round 8
// speedup vs baseline: 1.2168x; 1.0421x over previous
#include <cuda_runtime.h>
#include <cuda_fp16.h>
#include <math.h>
#include <stdint.h>

// Problem constants
#define BB 8
#define DD 512
#define SS 4096
#define FF 2048

// ---------------- static scratch (no allocations allowed) ----------------
// fp32
__device__ float g_y [(size_t)BB * SS * DD];
__device__ float g_h2[(size_t)BB * SS * DD];
__device__ double g_acc[32];
// fp16 operands (row-major [x][k] for every GEMM)
__device__ __half g_xh [(size_t)BB * SS * DD];   // x^T  [B,S,D]
__device__ __half g_qh [(size_t)BB * SS * DD];
__device__ __half g_kh [(size_t)BB * SS * DD];
__device__ __half g_vt [(size_t)BB * DD * SS];   // v^T  [B,D,S]
__device__ __half g_sh [(size_t)BB * SS * SS];   // scores/attn fp16
__device__ __half g_t1h[(size_t)BB * SS * DD];
__device__ __half g_yh [(size_t)BB * SS * DD];   // normalized post, fp16 copy
__device__ __half g_h1h[(size_t)BB * SS * FF];
__device__ __half g_wqT[DD * DD];
__device__ __half g_wkT[DD * DD];
__device__ __half g_wvT[DD * DD];
__device__ __half g_woT[DD * DD];
__device__ __half g_w1T[(size_t)DD * FF];        // [F,D]
__device__ __half g_w2T[(size_t)DD * FF];        // [D,F]

// ---------------- helpers ----------------
__device__ __forceinline__ uint32_t smem_u32(const void* p)
{
    uint32_t a;
    asm("{ .reg .u64 t; cvta.to.shared.u64 t, %1; cvt.u32.u64 %0, t; }" : "=r"(a) : "l"(p));
    return a;
}

#define CP16(d, s) asm volatile("cp.async.ca.shared.global [%0], [%1], 16;" :: "r"(d), "l"(s))
#define CPC()  asm volatile("cp.async.commit_group;" ::: "memory")
#define CPW0() asm volatile("cp.async.wait_group 0;" ::: "memory")
#define CPW1() asm volatile("cp.async.wait_group 1;" ::: "memory")

#define LDMX4(r, addr) \
    asm volatile("ldmatrix.sync.aligned.m8n8.x4.shared.b16 {%0,%1,%2,%3}, [%4];" \
        : "=r"((r)[0]), "=r"((r)[1]), "=r"((r)[2]), "=r"((r)[3]) : "r"(addr))

__device__ __forceinline__ void mma16816(float c[4], const uint32_t a[4],
                                         uint32_t b0, uint32_t b1)
{
    asm volatile(
        "mma.sync.aligned.m16n8k16.row.col.f32.f16.f16.f32 "
        "{%0,%1,%2,%3}, {%4,%5,%6,%7}, {%8,%9}, {%0,%1,%2,%3};\n"
        : "+f"(c[0]), "+f"(c[1]), "+f"(c[2]), "+f"(c[3])
        : "r"(a[0]), "r"(a[1]), "r"(a[2]), "r"(a[3]),
          "r"(b0), "r"(b1));
}

// ---------------- fp16 tensor-core GEMM, 2-stage cp.async + ldmatrix ----------------
// C[M,N] = A[M,K] * B[N,K]^T, A/B fp16 row-major. 128x128 tile, TK=64.
// EPI: 0 none, 1 +bias, 2 relu(+bias),
//      3 +residual from res[N,M]-layout (x^T, ld=SS) + stats -> fp32 out
//      4 +bias +residual from res[M,N]-layout (ld=DD) + stats -> fp32 out
// OUT: 0 fp32 [M,N]; 1 fp16 [M,N]; 2 fp16 transposed [N,M]
#define SKB 144                     // smem row stride in bytes
#define TILE_B (128 * SKB)          // 18432 bytes
#define SMEMB (4 * TILE_B)          // 73728 bytes (2 stages x (A+B)) -> 2 CTAs/SM

template <int EPI, int OUT>
__global__ __launch_bounds__(256)
void gemm_h(const __half* __restrict__ A, const __half* __restrict__ B,
            const float* __restrict__ bias, void* __restrict__ Cv,
            int K, int lda, int ldb, int ldc,
            long long sA, long long sB, long long sC,
            const float* __restrict__ res, long long sR, double* __restrict__ stats)
{
    extern __shared__ char smem[];
    const uint32_t base = smem_u32(smem);

    const int bz = blockIdx.z;
    const __half* Ab = A + (long long)bz * sA;
    const __half* Bb = B + (long long)bz * sB;

    const int m0 = blockIdx.y * 128;
    const int n0 = blockIdx.x * 128;
    const int tid  = threadIdx.x;
    const int lane = tid & 31;
    const int warp = tid >> 5;
    const int wm = (warp >> 2) * 64;
    const int wn = (warp & 3) * 32;
    const int qr = lane >> 2;   // 0..7
    const int qc = lane & 3;    // 0..3

    float acc[4][4][4];
#pragma unroll
    for (int i = 0; i < 4; i++)
#pragma unroll
        for (int j = 0; j < 4; j++)
#pragma unroll
            for (int q = 0; q < 4; q++) acc[i][j][q] = 0.f;

    const int NKB = K >> 6;

    // staging: each operand tile = 128 rows x 128B; 1024 16B chunks, 4/thread
    const int sx = tid >> 3;       // row 0..31 (+32 per iter)
    const int sc = tid & 7;        // 16B chunk in row
    const uint32_t sdst = (uint32_t)(sx * SKB + sc * 16);

#define STAGE(buf, k0)                                                          \
    do {                                                                        \
        const uint32_t aD = base + (buf) * TILE_B + sdst;                       \
        const uint32_t bD = base + (2 + (buf)) * TILE_B + sdst;                 \
        const __half* aSrc = Ab + (long long)(m0 + sx) * lda + (k0) + sc * 8;   \
        const __half* bSrc = Bb + (long long)(n0 + sx) * ldb + (k0) + sc * 8;   \
        _Pragma("unroll")                                                       \
        for (int it = 0; it < 4; it++) {                                        \
            CP16(aD + it * (32 * SKB), aSrc + (long long)(it * 32) * lda);      \
            CP16(bD + it * (32 * SKB), bSrc + (long long)(it * 32) * ldb);      \
        }                                                                       \
    } while (0)

    STAGE(0, 0);
    CPC();

    // per-lane ldmatrix offsets: lanes 0-15 -> rows (x&15) @ +0B, 16-31 -> @ +16B
    const uint32_t aOff = (uint32_t)((wm + (lane & 15)) * SKB + (lane >> 4) * 16);
    const uint32_t bOff = (uint32_t)((wn + (lane & 15)) * SKB + (lane >> 4) * 16);

    for (int kb = 0; kb < NKB; kb++) {
        const int cur = kb & 1;
        if (kb + 1 < NKB) {
            STAGE(cur ^ 1, (kb + 1) << 6);
            CPC();
            CPW1();
        } else {
            CPW0();
        }
        __syncthreads();

        const uint32_t aT = base + cur * TILE_B + aOff;
        const uint32_t bT = base + (2 + cur) * TILE_B + bOff;
#pragma unroll
        for (int ks = 0; ks < 4; ks++) {
            uint32_t af[4][4], bq[2][4];
#pragma unroll
            for (int mi = 0; mi < 4; mi++)
                LDMX4(af[mi], aT + mi * (16 * SKB) + ks * 32);
#pragma unroll
            for (int n2 = 0; n2 < 2; n2++)
                LDMX4(bq[n2], bT + n2 * (16 * SKB) + ks * 32);
#pragma unroll
            for (int mi = 0; mi < 4; mi++) {
                mma16816(acc[mi][0], af[mi], bq[0][0], bq[0][2]);
                mma16816(acc[mi][1], af[mi], bq[0][1], bq[0][3]);
                mma16816(acc[mi][2], af[mi], bq[1][0], bq[1][2]);
                mma16816(acc[mi][3], af[mi], bq[1][1], bq[1][3]);
            }
        }
        __syncthreads();
    }
#undef STAGE

    // ---- epilogue ----
    const float* resb = (EPI >= 3) ? (res + (long long)bz * sR) : nullptr;
    float ls = 0.f, lq = 0.f;

#pragma unroll
    for (int mi = 0; mi < 4; mi++) {
        const int m = m0 + wm + mi * 16 + qr;
#pragma unroll
        for (int ni = 0; ni < 4; ni++) {
            const int nc = n0 + wn + ni * 8 + 2 * qc;
            float c0 = acc[mi][ni][0], c1 = acc[mi][ni][1];
            float c2 = acc[mi][ni][2], c3 = acc[mi][ni][3];
            if (EPI == 1 || EPI == 2 || EPI == 4) {
                const float bx = bias[nc], by = bias[nc + 1];
                c0 += bx; c1 += by; c2 += bx; c3 += by;
            }
            if (EPI == 2) {
                c0 = fmaxf(c0, 0.f); c1 = fmaxf(c1, 0.f);
                c2 = fmaxf(c2, 0.f); c3 = fmaxf(c3, 0.f);
            }
            if (EPI == 3) {
                // residual stored [N, M] (x^T layout, ld = sR row stride = SS)
                c0 += resb[(long long)nc * SS + m];
                c1 += resb[(long long)(nc + 1) * SS + m];
                c2 += resb[(long long)nc * SS + m + 8];
                c3 += resb[(long long)(nc + 1) * SS + m + 8];
            }
            if (EPI == 4) {
                // residual stored [M, N] (ld = DD)
                const float2 r0 = *(const float2*)(resb + (long long)m * DD + nc);
                const float2 r1 = *(const float2*)(resb + (long long)(m + 8) * DD + nc);
                c0 += r0.x; c1 += r0.y; c2 += r1.x; c3 += r1.y;
            }
            if (EPI >= 3) {
                ls += c0 + c1 + c2 + c3;
                lq += c0 * c0 + c1 * c1 + c2 * c2 + c3 * c3;
            }
            if (OUT == 0) {
                float* C = (float*)Cv + (long long)bz * sC;
                float2 lo; lo.x = c0; lo.y = c1;
                float2 hi; hi.x = c2; hi.y = c3;
                *(float2*)(C + (long long)m * ldc + nc) = lo;
                *(float2*)(C + (long long)(m + 8) * ldc + nc) = hi;
            } else if (OUT == 1) {
                __half* C = (__half*)Cv + (long long)bz * sC;
                *(__half2*)(C + (long long)m * ldc + nc) = __floats2half2_rn(c0, c1);
                *(__half2*)(C + (long long)(m + 8) * ldc + nc) = __floats2half2_rn(c2, c3);
            } else {
                __half* C = (__half*)Cv + (long long)bz * sC;
                C[(long long)nc * ldc + m]           = __float2half_rn(c0);
                C[(long long)(nc + 1) * ldc + m]     = __float2half_rn(c1);
                C[(long long)nc * ldc + m + 8]       = __float2half_rn(c2);
                C[(long long)(nc + 1) * ldc + m + 8] = __float2half_rn(c3);
            }
        }
    }

    if (EPI >= 3) {
        // block-reduce ls/lq into per-batch stats (reuse GEMM smem; mainloop done)
        float* sa = (float*)smem;
        float* sb = sa + 256;
        sa[tid] = ls; sb[tid] = lq;
        __syncthreads();
        for (int o = 128; o > 0; o >>= 1) {
            if (tid < o) { sa[tid] += sa[tid + o]; sb[tid] += sb[tid + o]; }
            __syncthreads();
        }
        if (tid == 0) {
            atomicAdd(stats + 2 * bz + 0, (double)sa[0]);
            atomicAdd(stats + 2 * bz + 1, (double)sb[0]);
        }
    }
}

// ---------------- transpose + fp32->fp16 convert: src[R,C] -> dst[C,R] ----------------
__global__ void transpose_h(const float* __restrict__ src, __half* __restrict__ dst,
                            int R, int C)
{
    const int b = blockIdx.z;
    src += (long long)b * R * C;
    dst += (long long)b * R * C;
    const int r0 = blockIdx.y * 32;
    const int c0 = blockIdx.x * 32;
    __shared__ float t[32][33];
    const int tx = threadIdx.x, ty = threadIdx.y;   // 32 x 8
#pragma unroll
    for (int i = 0; i < 32; i += 8)
        t[ty + i][tx] = src[(long long)(r0 + ty + i) * C + c0 + tx];
    __syncthreads();
#pragma unroll
    for (int i = 0; i < 32; i += 8)
        dst[(long long)(c0 + ty + i) * R + r0 + tx] = __float2half_rn(t[tx][ty + i]);
}

// ---------------- softmax on fp16 scores (in place, scaled) ----------------
__global__ void softmax_h(__half* __restrict__ sh, float scale)
{
    const long long row = blockIdx.x;
    uint4* p = (uint4*)(sh + row * SS);       // 512 uint4 per row (8 halves each)
    const int tid = threadIdx.x;              // 256 threads, 2 uint4 each
    __shared__ float red[256];

    uint4 u[2];
    float f[16];
    u[0] = p[tid];
    u[1] = p[tid + 256];
#pragma unroll
    for (int ii = 0; ii < 2; ii++) {
        const uint32_t* w = (const uint32_t*)&u[ii];
#pragma unroll
        for (int j = 0; j < 4; j++) {
            float2 d = __half22float2(*(const __half2*)&w[j]);
            f[ii * 8 + j * 2]     = d.x;
            f[ii * 8 + j * 2 + 1] = d.y;
        }
    }
    float mx = -INFINITY;
#pragma unroll
    for (int i = 0; i < 16; i++) mx = fmaxf(mx, f[i]);
    red[tid] = mx; __syncthreads();
    for (int o = 128; o > 0; o >>= 1) {
        if (tid < o) red[tid] = fmaxf(red[tid], red[tid + o]);
        __syncthreads();
    }
    mx = red[0];
    __syncthreads();

    float sum = 0.f;
#pragma unroll
    for (int i = 0; i < 16; i++) {
        f[i] = __expf((f[i] - mx) * scale);
        sum += f[i];
    }
    red[tid] = sum; __syncthreads();
    for (int o = 128; o > 0; o >>= 1) {
        if (tid < o) red[tid] += red[tid + o];
        __syncthreads();
    }
    const float inv = 1.f / red[0];
#pragma unroll
    for (int ii = 0; ii < 2; ii++) {
        uint32_t* w = (uint32_t*)&u[ii];
#pragma unroll
        for (int j = 0; j < 4; j++) {
            __half2 h = __floats2half2_rn(f[ii * 8 + j * 2] * inv,
                                          f[ii * 8 + j * 2 + 1] * inv);
            w[j] = *(const uint32_t*)&h;
        }
    }
    p[tid]       = u[0];
    p[tid + 256] = u[1];
}

__global__ void zero_acc_kernel()
{
    if (threadIdx.x < 32) g_acc[threadIdx.x] = 0.0;
}

// normalize y in place (fp32) + write fp16 copy
__global__ void apply1_kernel(float* __restrict__ y, __half* __restrict__ yh)
{
    const int b = blockIdx.y;
    const double sum = g_acc[2 * b], sq = g_acc[2 * b + 1];
    const double NE = (double)SS * DD;
    const double mean = sum / NE;
    double var = sq - NE * mean * mean;
    if (var < 0.0) var = 0.0;
    const float inv = (float)(1.0 / (sqrt(var) + 1e-7));
    const float fm = (float)mean;

    float4* y4 = ((float4*)y) + (long long)b * (SS * DD / 4);
    __half2* yh2 = ((__half2*)yh) + (long long)b * (SS * DD / 2);
    const long long i = (long long)blockIdx.x * 256 + threadIdx.x;  // grid.x = 2048
    float4 vv = y4[i];
    vv.x = (vv.x - fm) * inv; vv.y = (vv.y - fm) * inv;
    vv.z = (vv.z - fm) * inv; vv.w = (vv.w - fm) * inv;
    y4[i] = vv;
    yh2[i * 2]     = __floats2half2_rn(vv.x, vv.y);
    yh2[i * 2 + 1] = __floats2half2_rn(vv.z, vv.w);
}

// out[b,d,s] = (y2[b,s,d] - mean) * inv
__global__ void apply2t_kernel(const float* __restrict__ y2, float* __restrict__ out)
{
    const int b = blockIdx.z;
    const double sum = g_acc[16 + 2 * b], sq = g_acc[16 + 2 * b + 1];
    const double NE = (double)SS * DD;
    const double mean = sum / NE;
    double var = sq - NE * mean * mean;
    if (var < 0.0) var = 0.0;
    const float inv = (float)(1.0 / (sqrt(var) + 1e-7));
    const float fm = (float)mean;

    const int s0 = blockIdx.x * 32;
    const int d0 = blockIdx.y * 32;
    __shared__ float ys[32][33];
    const int tx = threadIdx.x, ty = threadIdx.y;

#pragma unroll
    for (int i = 0; i < 32; i += 8)
        ys[ty + i][tx] = y2[((long long)b * SS + s0 + ty + i) * DD + d0 + tx];
    __syncthreads();
#pragma unroll
    for (int i = 0; i < 32; i += 8)
        out[((long long)b * DD + d0 + ty + i) * SS + s0 + tx] =
            (ys[tx][ty + i] - fm) * inv;
}

// ---------------- host-side orchestration ----------------
template <typename T>
static T* sym(const void* symbol)
{
    void* p = nullptr;
    cudaGetSymbolAddress(&p, symbol);
    return (T*)p;
}

extern "C" void kernel_launch(void* const* d_in, const int* in_sizes, int n_in,
                              void* d_out, int out_size)
{
    const float* x  = (const float*)d_in[0];
    const float* Wq = (const float*)d_in[1];
    const float* Wk = (const float*)d_in[2];
    const float* Wv = (const float*)d_in[3];
    const float* Wo = (const float*)d_in[4];
    const float* W1 = (const float*)d_in[5];
    const float* b1 = (const float*)d_in[6];
    const float* W2 = (const float*)d_in[7];
    const float* b2 = (const float*)d_in[8];
    float* out = (float*)d_out;

    float*  py   = sym<float>((const void*)g_y);
    float*  ph2  = sym<float>((const void*)g_h2);
    double* pacc = sym<double>((const void*)g_acc);
    __half* pxh  = sym<__half>((const void*)g_xh);
    __half* pqh  = sym<__half>((const void*)g_qh);
    __half* pkh  = sym<__half>((const void*)g_kh);
    __half* pvt  = sym<__half>((const void*)g_vt);
    __half* psh  = sym<__half>((const void*)g_sh);
    __half* pt1h = sym<__half>((const void*)g_t1h);
    __half* pyh  = sym<__half>((const void*)g_yh);
    __half* ph1h = sym<__half>((const void*)g_h1h);
    __half* pwqT = sym<__half>((const void*)g_wqT);
    __half* pwkT = sym<__half>((const void*)g_wkT);
    __half* pwvT = sym<__half>((const void*)g_wvT);
    __half* pwoT = sym<__half>((const void*)g_woT);
    __half* pw1T = sym<__half>((const void*)g_w1T);
    __half* pw2T = sym<__half>((const void*)g_w2T);

    const long long sSD = (long long)SS * DD;
    const long long sSS = (long long)SS * SS;
    const long long sSF = (long long)SS * FF;
    const long long sDS = (long long)DD * SS;

    cudaFuncSetAttribute(gemm_h<0, 1>, cudaFuncAttributeMaxDynamicSharedMemorySize, SMEMB);
    cudaFuncSetAttribute(gemm_h<0, 2>, cudaFuncAttributeMaxDynamicSharedMemorySize, SMEMB);
    cudaFuncSetAttribute(gemm_h<2, 1>, cudaFuncAttributeMaxDynamicSharedMemorySize, SMEMB);
    cudaFuncSetAttribute(gemm_h<3, 0>, cudaFuncAttributeMaxDynamicSharedMemorySize, SMEMB);
    cudaFuncSetAttribute(gemm_h<4, 0>, cudaFuncAttributeMaxDynamicSharedMemorySize, SMEMB);

    zero_acc_kernel<<<1, 32>>>();

    // pre-pass: fp16 transposed operands
    dim3 tblk(32, 8);
    transpose_h<<<dim3(SS / 32, DD / 32, BB), tblk>>>(x,  pxh,  DD, SS); // x[b]:[D,S]->[S,D]
    transpose_h<<<dim3(DD / 32, DD / 32, 1), tblk>>>(Wq, pwqT, DD, DD);
    transpose_h<<<dim3(DD / 32, DD / 32, 1), tblk>>>(Wk, pwkT, DD, DD);
    transpose_h<<<dim3(DD / 32, DD / 32, 1), tblk>>>(Wv, pwvT, DD, DD);
    transpose_h<<<dim3(DD / 32, DD / 32, 1), tblk>>>(Wo, pwoT, DD, DD);
    transpose_h<<<dim3(FF / 32, DD / 32, 1), tblk>>>(W1, pw1T, DD, FF); // [D,F]->[F,D]
    transpose_h<<<dim3(DD / 32, FF / 32, 1), tblk>>>(W2, pw2T, FF, DD); // [F,D]->[D,F]

    dim3 blk(256);
    dim3 gNarrow(DD / 128, SS / 128, BB);   // (4,32,8)
    dim3 gScore(SS / 128, SS / 128, BB);    // (32,32,8)
    dim3 gFFN(FF / 128, SS / 128, BB);      // (16,32,8)

    // q,k = xh @ WT  (fp16 out)
    gemm_h<0, 1><<<gNarrow, blk, SMEMB>>>(pxh, pwqT, nullptr, pqh,
        DD, DD, DD, DD, sSD, 0, sSD, nullptr, 0, nullptr);
    gemm_h<0, 1><<<gNarrow, blk, SMEMB>>>(pxh, pwkT, nullptr, pkh,
        DD, DD, DD, DD, sSD, 0, sSD, nullptr, 0, nullptr);
    // v = xh @ WvT (fp16 out, transposed to [D,S])
    gemm_h<0, 2><<<gNarrow, blk, SMEMB>>>(pxh, pwvT, nullptr, pvt,
        DD, DD, DD, SS, sSD, 0, sDS, nullptr, 0, nullptr);

    // scores = q @ k^T (fp16 out, in place softmax next)
    gemm_h<0, 1><<<gScore, blk, SMEMB>>>(pqh, pkh, nullptr, psh,
        DD, DD, DD, SS, sSD, sSD, sSS, nullptr, 0, nullptr);

    softmax_h<<<BB * SS, 256>>>(psh, 0.04419417382415922f /* 1/sqrt(512) */);

    // t1 = attn @ v  (A=[S,S], B=vT[D,S]; fp16 out)
    gemm_h<0, 1><<<gNarrow, blk, SMEMB>>>(psh, pvt, nullptr, pt1h,
        SS, SS, SS, DD, sSS, sDS, sSD, nullptr, 0, nullptr);

    // y = t1 @ Wo + x^T  (fused residual + stats stage 0, fp32 out)
    gemm_h<3, 0><<<gNarrow, blk, SMEMB>>>(pt1h, pwoT, nullptr, py,
        DD, DD, DD, DD, sSD, 0, sSD, x, sDS, pacc);

    apply1_kernel<<<dim3(2048, BB), 256>>>(py, pyh);

    // FFN
    gemm_h<2, 1><<<gFFN, blk, SMEMB>>>(pyh, pw1T, b1, ph1h,
        DD, DD, DD, FF, sSD, 0, sSF, nullptr, 0, nullptr);
    // h2 = h1 @ W2 + b2 + y  (fused residual + stats stage 1, fp32 out)
    gemm_h<4, 0><<<gNarrow, blk, SMEMB>>>(ph1h, pw2T, b2, ph2,
        FF, FF, FF, DD, sSF, 0, sSD, py, sSD, pacc + 16);

    apply2t_kernel<<<dim3(SS / 32, DD / 32, BB), tblk>>>(ph2, out);

    (void)in_sizes; (void)n_in; (void)out_size;
}

// round 9
// speedup vs baseline: 1.2499x; 1.0272x over previous
#include <cuda_runtime.h>
#include <cuda_fp16.h>
#include <math.h>
#include <stdint.h>

// Problem constants
#define BB 8
#define DD 512
#define SS 4096
#define FF 2048

// ---------------- static scratch (no allocations allowed) ----------------
// fp32
__device__ float g_y [(size_t)BB * SS * DD];
__device__ float g_h2[(size_t)BB * SS * DD];
__device__ double g_acc[32];
// fp16 operands (row-major [x][k] for every GEMM)
__device__ __half g_xh  [(size_t)BB * SS * DD];   // x^T  [B,S,D]
__device__ __half g_qh  [(size_t)BB * SS * DD];
__device__ __half g_kh  [(size_t)BB * SS * DD];
__device__ __half g_vt  [(size_t)BB * DD * SS];   // v'^T [B,D,S]  (v' = x^T Wv Wo)
__device__ __half g_sh  [(size_t)BB * SS * SS];   // scores/attn fp16
__device__ __half g_yh  [(size_t)BB * SS * DD];   // normalized post, fp16 copy
__device__ __half g_h1h [(size_t)BB * SS * FF];
__device__ __half g_wqT [DD * DD];
__device__ __half g_wkT [DD * DD];
__device__ __half g_wvh [DD * DD];                // Wv fp16, NOT transposed
__device__ __half g_woT [DD * DD];
__device__ __half g_wvoT[DD * DD];                // (Wv@Wo)^T fp16
__device__ __half g_w1T [(size_t)DD * FF];        // [F,D]
__device__ __half g_w2T [(size_t)DD * FF];        // [D,F]

// ---------------- helpers ----------------
__device__ __forceinline__ uint32_t smem_u32(const void* p)
{
    uint32_t a;
    asm("{ .reg .u64 t; cvta.to.shared.u64 t, %1; cvt.u32.u64 %0, t; }" : "=r"(a) : "l"(p));
    return a;
}

#define CP16(d, s) asm volatile("cp.async.ca.shared.global [%0], [%1], 16;" :: "r"(d), "l"(s))
#define CPC()  asm volatile("cp.async.commit_group;" ::: "memory")
#define CPW0() asm volatile("cp.async.wait_group 0;" ::: "memory")
#define CPW1() asm volatile("cp.async.wait_group 1;" ::: "memory")

#define LDMX4(r, addr) \
    asm volatile("ldmatrix.sync.aligned.m8n8.x4.shared.b16 {%0,%1,%2,%3}, [%4];" \
        : "=r"((r)[0]), "=r"((r)[1]), "=r"((r)[2]), "=r"((r)[3]) : "r"(addr))

__device__ __forceinline__ void mma16816(float c[4], const uint32_t a[4],
                                         uint32_t b0, uint32_t b1)
{
    asm volatile(
        "mma.sync.aligned.m16n8k16.row.col.f32.f16.f16.f32 "
        "{%0,%1,%2,%3}, {%4,%5,%6,%7}, {%8,%9}, {%0,%1,%2,%3};\n"
        : "+f"(c[0]), "+f"(c[1]), "+f"(c[2]), "+f"(c[3])
        : "r"(a[0]), "r"(a[1]), "r"(a[2]), "r"(a[3]),
          "r"(b0), "r"(b1));
}

// ---------------- fp16 tensor-core GEMM, 2-stage cp.async + ldmatrix ----------------
// C[M,N] = A[M,K] * B[N,K]^T, A/B fp16 row-major. 128x128 tile, TK=64.
// EPI: 0 none, 1 +bias, 2 relu(+bias),
//      3 +residual from res[N,M]-layout (x^T, ld=SS) + stats -> fp32 out
//      4 +bias +residual from res[M,N]-layout (ld=DD) + stats -> fp32 out
// OUT: 0 fp32 [M,N]; 1 fp16 [M,N]; 2 fp16 transposed [N,M]
#define SKB 144                     // smem row stride in bytes
#define TILE_B (128 * SKB)          // 18432 bytes
#define SMEMB (4 * TILE_B)          // 73728 bytes (2 stages x (A+B)) -> 2 CTAs/SM

template <int EPI, int OUT>
__global__ __launch_bounds__(256)
void gemm_h(const __half* __restrict__ A, const __half* __restrict__ B,
            const float* __restrict__ bias, void* __restrict__ Cv,
            int K, int lda, int ldb, int ldc,
            long long sA, long long sB, long long sC,
            const float* __restrict__ res, long long sR, double* __restrict__ stats)
{
    extern __shared__ char smem[];
    const uint32_t base = smem_u32(smem);

    const int bz = blockIdx.z;
    const __half* Ab = A + (long long)bz * sA;
    const __half* Bb = B + (long long)bz * sB;

    const int m0 = blockIdx.y * 128;
    const int n0 = blockIdx.x * 128;
    const int tid  = threadIdx.x;
    const int lane = tid & 31;
    const int warp = tid >> 5;
    const int wm = (warp >> 2) * 64;
    const int wn = (warp & 3) * 32;
    const int qr = lane >> 2;   // 0..7
    const int qc = lane & 3;    // 0..3

    float acc[4][4][4];
#pragma unroll
    for (int i = 0; i < 4; i++)
#pragma unroll
        for (int j = 0; j < 4; j++)
#pragma unroll
            for (int q = 0; q < 4; q++) acc[i][j][q] = 0.f;

    const int NKB = K >> 6;

    // staging: each operand tile = 128 rows x 128B; 1024 16B chunks, 4/thread
    const int sx = tid >> 3;       // row 0..31 (+32 per iter)
    const int sc = tid & 7;        // 16B chunk in row
    const uint32_t sdst = (uint32_t)(sx * SKB + sc * 16);

#define STAGE(buf, k0)                                                          \
    do {                                                                        \
        const uint32_t aD = base + (buf) * TILE_B + sdst;                       \
        const uint32_t bD = base + (2 + (buf)) * TILE_B + sdst;                 \
        const __half* aSrc = Ab + (long long)(m0 + sx) * lda + (k0) + sc * 8;   \
        const __half* bSrc = Bb + (long long)(n0 + sx) * ldb + (k0) + sc * 8;   \
        _Pragma("unroll")                                                       \
        for (int it = 0; it < 4; it++) {                                        \
            CP16(aD + it * (32 * SKB), aSrc + (long long)(it * 32) * lda);      \
            CP16(bD + it * (32 * SKB), bSrc + (long long)(it * 32) * ldb);      \
        }                                                                       \
    } while (0)

    STAGE(0, 0);
    CPC();

    // per-lane ldmatrix offsets: lanes 0-15 -> rows (x&15) @ +0B, 16-31 -> @ +16B
    const uint32_t aOff = (uint32_t)((wm + (lane & 15)) * SKB + (lane >> 4) * 16);
    const uint32_t bOff = (uint32_t)((wn + (lane & 15)) * SKB + (lane >> 4) * 16);

    for (int kb = 0; kb < NKB; kb++) {
        const int cur = kb & 1;
        if (kb + 1 < NKB) {
            STAGE(cur ^ 1, (kb + 1) << 6);
            CPC();
            CPW1();
        } else {
            CPW0();
        }
        __syncthreads();

        const uint32_t aT = base + cur * TILE_B + aOff;
        const uint32_t bT = base + (2 + cur) * TILE_B + bOff;
#pragma unroll
        for (int ks = 0; ks < 4; ks++) {
            uint32_t af[4][4], bq[2][4];
#pragma unroll
            for (int mi = 0; mi < 4; mi++)
                LDMX4(af[mi], aT + mi * (16 * SKB) + ks * 32);
#pragma unroll
            for (int n2 = 0; n2 < 2; n2++)
                LDMX4(bq[n2], bT + n2 * (16 * SKB) + ks * 32);
#pragma unroll
            for (int mi = 0; mi < 4; mi++) {
                mma16816(acc[mi][0], af[mi], bq[0][0], bq[0][2]);
                mma16816(acc[mi][1], af[mi], bq[0][1], bq[0][3]);
                mma16816(acc[mi][2], af[mi], bq[1][0], bq[1][2]);
                mma16816(acc[mi][3], af[mi], bq[1][1], bq[1][3]);
            }
        }
        __syncthreads();
    }
#undef STAGE

    // ---- epilogue ----
    const float* resb = (EPI >= 3) ? (res + (long long)bz * sR) : nullptr;
    float ls = 0.f, lq = 0.f;

#pragma unroll
    for (int mi = 0; mi < 4; mi++) {
        const int m = m0 + wm + mi * 16 + qr;
#pragma unroll
        for (int ni = 0; ni < 4; ni++) {
            const int nc = n0 + wn + ni * 8 + 2 * qc;
            float c0 = acc[mi][ni][0], c1 = acc[mi][ni][1];
            float c2 = acc[mi][ni][2], c3 = acc[mi][ni][3];
            if (EPI == 1 || EPI == 2 || EPI == 4) {
                const float bx = bias[nc], by = bias[nc + 1];
                c0 += bx; c1 += by; c2 += bx; c3 += by;
            }
            if (EPI == 2) {
                c0 = fmaxf(c0, 0.f); c1 = fmaxf(c1, 0.f);
                c2 = fmaxf(c2, 0.f); c3 = fmaxf(c3, 0.f);
            }
            if (EPI == 3) {
                // residual stored [N, M] (x^T layout, ld = sR row stride = SS)
                c0 += resb[(long long)nc * SS + m];
                c1 += resb[(long long)(nc + 1) * SS + m];
                c2 += resb[(long long)nc * SS + m + 8];
                c3 += resb[(long long)(nc + 1) * SS + m + 8];
            }
            if (EPI == 4) {
                // residual stored [M, N] (ld = DD)
                const float2 r0 = *(const float2*)(resb + (long long)m * DD + nc);
                const float2 r1 = *(const float2*)(resb + (long long)(m + 8) * DD + nc);
                c0 += r0.x; c1 += r0.y; c2 += r1.x; c3 += r1.y;
            }
            if (EPI >= 3) {
                ls += c0 + c1 + c2 + c3;
                lq += c0 * c0 + c1 * c1 + c2 * c2 + c3 * c3;
            }
            if (OUT == 0) {
                float* C = (float*)Cv + (long long)bz * sC;
                float2 lo; lo.x = c0; lo.y = c1;
                float2 hi; hi.x = c2; hi.y = c3;
                *(float2*)(C + (long long)m * ldc + nc) = lo;
                *(float2*)(C + (long long)(m + 8) * ldc + nc) = hi;
            } else if (OUT == 1) {
                __half* C = (__half*)Cv + (long long)bz * sC;
                *(__half2*)(C + (long long)m * ldc + nc) = __floats2half2_rn(c0, c1);
                *(__half2*)(C + (long long)(m + 8) * ldc + nc) = __floats2half2_rn(c2, c3);
            } else {
                __half* C = (__half*)Cv + (long long)bz * sC;
                C[(long long)nc * ldc + m]           = __float2half_rn(c0);
                C[(long long)(nc + 1) * ldc + m]     = __float2half_rn(c1);
                C[(long long)nc * ldc + m + 8]       = __float2half_rn(c2);
                C[(long long)(nc + 1) * ldc + m + 8] = __float2half_rn(c3);
            }
        }
    }

    if (EPI >= 3) {
        // block-reduce ls/lq into per-batch stats (reuse GEMM smem; mainloop done)
        float* sa = (float*)smem;
        float* sb = sa + 256;
        sa[tid] = ls; sb[tid] = lq;
        __syncthreads();
        for (int o = 128; o > 0; o >>= 1) {
            if (tid < o) { sa[tid] += sa[tid + o]; sb[tid] += sb[tid + o]; }
            __syncthreads();
        }
        if (tid == 0) {
            atomicAdd(stats + 2 * bz + 0, (double)sa[0]);
            atomicAdd(stats + 2 * bz + 1, (double)sb[0]);
        }
    }
}

// ---------------- transpose + fp32->fp16 convert: src[R,C] -> dst[C,R] ----------------
__global__ void transpose_h(const float* __restrict__ src, __half* __restrict__ dst,
                            int R, int C)
{
    const int b = blockIdx.z;
    src += (long long)b * R * C;
    dst += (long long)b * R * C;
    const int r0 = blockIdx.y * 32;
    const int c0 = blockIdx.x * 32;
    __shared__ float t[32][33];
    const int tx = threadIdx.x, ty = threadIdx.y;   // 32 x 8
#pragma unroll
    for (int i = 0; i < 32; i += 8)
        t[ty + i][tx] = src[(long long)(r0 + ty + i) * C + c0 + tx];
    __syncthreads();
#pragma unroll
    for (int i = 0; i < 32; i += 8)
        dst[(long long)(c0 + ty + i) * R + r0 + tx] = __float2half_rn(t[tx][ty + i]);
}

// ---------------- straight fp32->fp16 convert ----------------
__global__ void convert_h(const float* __restrict__ src, __half* __restrict__ dst)
{
    const long long i = (long long)blockIdx.x * 256 + threadIdx.x;
    const float4 v = ((const float4*)src)[i];
    __half2* d = (__half2*)dst + i * 2;
    d[0] = __floats2half2_rn(v.x, v.y);
    d[1] = __floats2half2_rn(v.z, v.w);
}

// ---------------- softmax on fp16 scores (in place, scaled) ----------------
__global__ void softmax_h(__half* __restrict__ sh, float scale)
{
    const long long row = blockIdx.x;
    uint4* p = (uint4*)(sh + row * SS);       // 512 uint4 per row (8 halves each)
    const int tid = threadIdx.x;              // 256 threads, 2 uint4 each
    __shared__ float red[256];

    uint4 u[2];
    float f[16];
    u[0] = p[tid];
    u[1] = p[tid + 256];
#pragma unroll
    for (int ii = 0; ii < 2; ii++) {
        const uint32_t* w = (const uint32_t*)&u[ii];
#pragma unroll
        for (int j = 0; j < 4; j++) {
            float2 d = __half22float2(*(const __half2*)&w[j]);
            f[ii * 8 + j * 2]     = d.x;
            f[ii * 8 + j * 2 + 1] = d.y;
        }
    }
    float mx = -INFINITY;
#pragma unroll
    for (int i = 0; i < 16; i++) mx = fmaxf(mx, f[i]);
    red[tid] = mx; __syncthreads();
    for (int o = 128; o > 0; o >>= 1) {
        if (tid < o) red[tid] = fmaxf(red[tid], red[tid + o]);
        __syncthreads();
    }
    mx = red[0];
    __syncthreads();

    float sum = 0.f;
#pragma unroll
    for (int i = 0; i < 16; i++) {
        f[i] = __expf((f[i] - mx) * scale);
        sum += f[i];
    }
    red[tid] = sum; __syncthreads();
    for (int o = 128; o > 0; o >>= 1) {
        if (tid < o) red[tid] += red[tid + o];
        __syncthreads();
    }
    const float inv = 1.f / red[0];
#pragma unroll
    for (int ii = 0; ii < 2; ii++) {
        uint32_t* w = (uint32_t*)&u[ii];
#pragma unroll
        for (int j = 0; j < 4; j++) {
            __half2 h = __floats2half2_rn(f[ii * 8 + j * 2] * inv,
                                          f[ii * 8 + j * 2 + 1] * inv);
            w[j] = *(const uint32_t*)&h;
        }
    }
    p[tid]       = u[0];
    p[tid + 256] = u[1];
}

__global__ void zero_acc_kernel()
{
    if (threadIdx.x < 32) g_acc[threadIdx.x] = 0.0;
}

// normalize y in place (fp32) + write fp16 copy
__global__ void apply1_kernel(float* __restrict__ y, __half* __restrict__ yh)
{
    const int b = blockIdx.y;
    const double sum = g_acc[2 * b], sq = g_acc[2 * b + 1];
    const double NE = (double)SS * DD;
    const double mean = sum / NE;
    double var = sq - NE * mean * mean;
    if (var < 0.0) var = 0.0;
    const float inv = (float)(1.0 / (sqrt(var) + 1e-7));
    const float fm = (float)mean;

    float4* y4 = ((float4*)y) + (long long)b * (SS * DD / 4);
    __half2* yh2 = ((__half2*)yh) + (long long)b * (SS * DD / 2);
    const long long i = (long long)blockIdx.x * 256 + threadIdx.x;  // grid.x = 2048
    float4 vv = y4[i];
    vv.x = (vv.x - fm) * inv; vv.y = (vv.y - fm) * inv;
    vv.z = (vv.z - fm) * inv; vv.w = (vv.w - fm) * inv;
    y4[i] = vv;
    yh2[i * 2]     = __floats2half2_rn(vv.x, vv.y);
    yh2[i * 2 + 1] = __floats2half2_rn(vv.z, vv.w);
}

// out[b,d,s] = (y2[b,s,d] - mean) * inv
__global__ void apply2t_kernel(const float* __restrict__ y2, float* __restrict__ out)
{
    const int b = blockIdx.z;
    const double sum = g_acc[16 + 2 * b], sq = g_acc[16 + 2 * b + 1];
    const double NE = (double)SS * DD;
    const double mean = sum / NE;
    double var = sq - NE * mean * mean;
    if (var < 0.0) var = 0.0;
    const float inv = (float)(1.0 / (sqrt(var) + 1e-7));
    const float fm = (float)mean;

    const int s0 = blockIdx.x * 32;
    const int d0 = blockIdx.y * 32;
    __shared__ float ys[32][33];
    const int tx = threadIdx.x, ty = threadIdx.y;

#pragma unroll
    for (int i = 0; i < 32; i += 8)
        ys[ty + i][tx] = y2[((long long)b * SS + s0 + ty + i) * DD + d0 + tx];
    __syncthreads();
#pragma unroll
    for (int i = 0; i < 32; i += 8)
        out[((long long)b * DD + d0 + ty + i) * SS + s0 + tx] =
            (ys[tx][ty + i] - fm) * inv;
}

// ---------------- host-side orchestration ----------------
template <typename T>
static T* sym(const void* symbol)
{
    void* p = nullptr;
    cudaGetSymbolAddress(&p, symbol);
    return (T*)p;
}

extern "C" void kernel_launch(void* const* d_in, const int* in_sizes, int n_in,
                              void* d_out, int out_size)
{
    const float* x  = (const float*)d_in[0];
    const float* Wq = (const float*)d_in[1];
    const float* Wk = (const float*)d_in[2];
    const float* Wv = (const float*)d_in[3];
    const float* Wo = (const float*)d_in[4];
    const float* W1 = (const float*)d_in[5];
    const float* b1 = (const float*)d_in[6];
    const float* W2 = (const float*)d_in[7];
    const float* b2 = (const float*)d_in[8];
    float* out = (float*)d_out;

    float*  py    = sym<float>((const void*)g_y);
    float*  ph2   = sym<float>((const void*)g_h2);
    double* pacc  = sym<double>((const void*)g_acc);
    __half* pxh   = sym<__half>((const void*)g_xh);
    __half* pqh   = sym<__half>((const void*)g_qh);
    __half* pkh   = sym<__half>((const void*)g_kh);
    __half* pvt   = sym<__half>((const void*)g_vt);
    __half* psh   = sym<__half>((const void*)g_sh);
    __half* pyh   = sym<__half>((const void*)g_yh);
    __half* ph1h  = sym<__half>((const void*)g_h1h);
    __half* pwqT  = sym<__half>((const void*)g_wqT);
    __half* pwkT  = sym<__half>((const void*)g_wkT);
    __half* pwvh  = sym<__half>((const void*)g_wvh);
    __half* pwoT  = sym<__half>((const void*)g_woT);
    __half* pwvoT = sym<__half>((const void*)g_wvoT);
    __half* pw1T  = sym<__half>((const void*)g_w1T);
    __half* pw2T  = sym<__half>((const void*)g_w2T);

    const long long sSD = (long long)SS * DD;
    const long long sSS = (long long)SS * SS;
    const long long sSF = (long long)SS * FF;
    const long long sDS = (long long)DD * SS;

    cudaFuncSetAttribute(gemm_h<0, 1>, cudaFuncAttributeMaxDynamicSharedMemorySize, SMEMB);
    cudaFuncSetAttribute(gemm_h<0, 2>, cudaFuncAttributeMaxDynamicSharedMemorySize, SMEMB);
    cudaFuncSetAttribute(gemm_h<2, 1>, cudaFuncAttributeMaxDynamicSharedMemorySize, SMEMB);
    cudaFuncSetAttribute(gemm_h<3, 0>, cudaFuncAttributeMaxDynamicSharedMemorySize, SMEMB);
    cudaFuncSetAttribute(gemm_h<4, 0>, cudaFuncAttributeMaxDynamicSharedMemorySize, SMEMB);

    zero_acc_kernel<<<1, 32>>>();

    // pre-pass: fp16 operands
    dim3 tblk(32, 8);
    transpose_h<<<dim3(SS / 32, DD / 32, BB), tblk>>>(x,  pxh,  DD, SS); // x[b]:[D,S]->[S,D]
    transpose_h<<<dim3(DD / 32, DD / 32, 1), tblk>>>(Wq, pwqT, DD, DD);
    transpose_h<<<dim3(DD / 32, DD / 32, 1), tblk>>>(Wk, pwkT, DD, DD);
    transpose_h<<<dim3(DD / 32, DD / 32, 1), tblk>>>(Wo, pwoT, DD, DD);
    convert_h<<<DD * DD / 1024, 256>>>(Wv, pwvh);                        // Wv fp16 (no transpose)
    transpose_h<<<dim3(FF / 32, DD / 32, 1), tblk>>>(W1, pw1T, DD, FF); // [D,F]->[F,D]
    transpose_h<<<dim3(DD / 32, FF / 32, 1), tblk>>>(W2, pw2T, FF, DD); // [F,D]->[D,F]

    dim3 blk(256);
    dim3 gW(DD / 128, DD / 128, 1);         // (4,4,1) weight-product GEMM
    dim3 gNarrow(DD / 128, SS / 128, BB);   // (4,32,8)
    dim3 gScore(SS / 128, SS / 128, BB);    // (32,32,8)
    dim3 gFFN(FF / 128, SS / 128, BB);      // (16,32,8)

    // W_voT[m,n] = sum_k WoT[m,k] * Wv[n,k]  ( = (Wv@Wo)^T )
    gemm_h<0, 1><<<gW, blk, SMEMB>>>(pwoT, pwvh, nullptr, pwvoT,
        DD, DD, DD, DD, 0, 0, 0, nullptr, 0, nullptr);

    // q,k = xh @ WT  (fp16 out)
    gemm_h<0, 1><<<gNarrow, blk, SMEMB>>>(pxh, pwqT, nullptr, pqh,
        DD, DD, DD, DD, sSD, 0, sSD, nullptr, 0, nullptr);
    gemm_h<0, 1><<<gNarrow, blk, SMEMB>>>(pxh, pwkT, nullptr, pkh,
        DD, DD, DD, DD, sSD, 0, sSD, nullptr, 0, nullptr);
    // v' = xh @ (WvWo)^T (fp16 out, transposed to [D,S])
    gemm_h<0, 2><<<gNarrow, blk, SMEMB>>>(pxh, pwvoT, nullptr, pvt,
        DD, DD, DD, SS, sSD, 0, sDS, nullptr, 0, nullptr);

    // scores = q @ k^T (fp16 out, in place softmax next)
    gemm_h<0, 1><<<gScore, blk, SMEMB>>>(pqh, pkh, nullptr, psh,
        DD, DD, DD, SS, sSD, sSD, sSS, nullptr, 0, nullptr);

    softmax_h<<<BB * SS, 256>>>(psh, 0.04419417382415922f /* 1/sqrt(512) */);

    // y = attn @ v' + x^T  (fused residual + stats stage 0, fp32 out)
    gemm_h<3, 0><<<gNarrow, blk, SMEMB>>>(psh, pvt, nullptr, py,
        SS, SS, SS, DD, sSS, sDS, sSD, x, sDS, pacc);

    apply1_kernel<<<dim3(2048, BB), 256>>>(py, pyh);

    // FFN
    gemm_h<2, 1><<<gFFN, blk, SMEMB>>>(pyh, pw1T, b1, ph1h,
        DD, DD, DD, FF, sSD, 0, sSF, nullptr, 0, nullptr);
    // h2 = h1 @ W2 + b2 + y  (fused residual + stats stage 1, fp32 out)
    gemm_h<4, 0><<<gNarrow, blk, SMEMB>>>(ph1h, pw2T, b2, ph2,
        FF, FF, FF, DD, sSF, 0, sSD, py, sSD, pacc + 16);

    apply2t_kernel<<<dim3(SS / 32, DD / 32, BB), tblk>>>(ph2, out);

    (void)in_sizes; (void)n_in; (void)out_size;
}

// round 10
// speedup vs baseline: 1.2844x; 1.0276x over previous
#include <cuda_runtime.h>
#include <cuda_fp16.h>
#include <math.h>
#include <stdint.h>

// Problem constants
#define BB 8
#define DD 512
#define SS 4096
#define FF 2048

// ---------------- static scratch (no allocations allowed) ----------------
// fp32
__device__ float g_y [(size_t)BB * SS * DD];
__device__ float g_h2[(size_t)BB * SS * DD];
__device__ double g_acc[32];
// fp16 operands (row-major [x][k] for every GEMM)
__device__ __half g_xh  [(size_t)BB * SS * DD];   // x^T  [B,S,D]
__device__ __half g_qh  [(size_t)BB * SS * DD];
__device__ __half g_kh  [(size_t)BB * SS * DD];
__device__ __half g_vt  [(size_t)BB * DD * SS];   // v'^T [B,D,S]  (v' = x^T Wv Wo)
__device__ __half g_sh  [(size_t)BB * SS * SS];   // scores/attn fp16
__device__ __half g_yh  [(size_t)BB * SS * DD];   // normalized post, fp16 copy
__device__ __half g_h1h [(size_t)BB * SS * FF];
__device__ __half g_wqT [DD * DD];
__device__ __half g_wkT [DD * DD];
__device__ __half g_wvh [DD * DD];                // Wv fp16, NOT transposed
__device__ __half g_woT [DD * DD];
__device__ __half g_wvoT[DD * DD];                // (Wv@Wo)^T fp16
__device__ __half g_w1T [(size_t)DD * FF];        // [F,D]
__device__ __half g_w2T [(size_t)DD * FF];        // [D,F]

// ---------------- helpers ----------------
__device__ __forceinline__ uint32_t smem_u32(const void* p)
{
    uint32_t a;
    asm("{ .reg .u64 t; cvta.to.shared.u64 t, %1; cvt.u32.u64 %0, t; }" : "=r"(a) : "l"(p));
    return a;
}

#define CP16(d, s) asm volatile("cp.async.ca.shared.global [%0], [%1], 16;" :: "r"(d), "l"(s))
#define CPC()  asm volatile("cp.async.commit_group;" ::: "memory")
#define CPW0() asm volatile("cp.async.wait_group 0;" ::: "memory")
#define CPW1() asm volatile("cp.async.wait_group 1;" ::: "memory")

#define LDMX4(r, addr) \
    asm volatile("ldmatrix.sync.aligned.m8n8.x4.shared.b16 {%0,%1,%2,%3}, [%4];" \
        : "=r"((r)[0]), "=r"((r)[1]), "=r"((r)[2]), "=r"((r)[3]) : "r"(addr))

__device__ __forceinline__ void mma16816(float c[4], const uint32_t a[4],
                                         uint32_t b0, uint32_t b1)
{
    asm volatile(
        "mma.sync.aligned.m16n8k16.row.col.f32.f16.f16.f32 "
        "{%0,%1,%2,%3}, {%4,%5,%6,%7}, {%8,%9}, {%0,%1,%2,%3};\n"
        : "+f"(c[0]), "+f"(c[1]), "+f"(c[2]), "+f"(c[3])
        : "r"(a[0]), "r"(a[1]), "r"(a[2]), "r"(a[3]),
          "r"(b0), "r"(b1));
}

// ---------------- fp16 tensor-core GEMM, 2-stage cp.async + ldmatrix ----------------
// 128 threads (4 warps), warp tile 64x64, CTA tile 128x128, TK=64.
// C[M,N] = A[M,K] * B[N,K]^T, A/B fp16 row-major.
// EPI: 0 none, 1 +bias, 2 relu(+bias),
//      3 +residual from res[N,M]-layout (x^T, ld=SS) + stats -> fp32 out
//      4 +bias +residual from res[M,N]-layout (ld=DD) + stats -> fp32 out
// OUT: 0 fp32 [M,N]; 1 fp16 [M,N]; 2 fp16 transposed [N,M]
#define SKB 144                     // smem row stride in bytes
#define TILE_B (128 * SKB)          // 18432 bytes
#define SMEMB (4 * TILE_B)          // 73728 bytes (2 stages x (A+B)) -> 2 CTAs/SM

template <int EPI, int OUT>
__global__ __launch_bounds__(128)
void gemm_h(const __half* __restrict__ A, const __half* __restrict__ B,
            const float* __restrict__ bias, void* __restrict__ Cv,
            int K, int lda, int ldb, int ldc,
            long long sA, long long sB, long long sC,
            const float* __restrict__ res, long long sR, double* __restrict__ stats)
{
    extern __shared__ char smem[];
    const uint32_t base = smem_u32(smem);

    const int bz = blockIdx.z;
    const __half* Ab = A + (long long)bz * sA;
    const __half* Bb = B + (long long)bz * sB;

    const int m0 = blockIdx.y * 128;
    const int n0 = blockIdx.x * 128;
    const int tid  = threadIdx.x;
    const int lane = tid & 31;
    const int warp = tid >> 5;
    const int wm = (warp >> 1) * 64;   // 0 / 64
    const int wn = (warp & 1) * 64;    // 0 / 64
    const int qr = lane >> 2;   // 0..7
    const int qc = lane & 3;    // 0..3

    float acc[4][8][4];
#pragma unroll
    for (int i = 0; i < 4; i++)
#pragma unroll
        for (int j = 0; j < 8; j++)
#pragma unroll
            for (int q = 0; q < 4; q++) acc[i][j][q] = 0.f;

    const int NKB = K >> 6;

    // staging: each operand tile = 128 rows x 128B; 1024 16B chunks, 8/thread
    const int sx = tid >> 3;       // row 0..15 (+16 per iter)
    const int sc = tid & 7;        // 16B chunk in row
    const uint32_t sdst = (uint32_t)(sx * SKB + sc * 16);

#define STAGE(buf, k0)                                                          \
    do {                                                                        \
        const uint32_t aD = base + (buf) * TILE_B + sdst;                       \
        const uint32_t bD = base + (2 + (buf)) * TILE_B + sdst;                 \
        const __half* aSrc = Ab + (long long)(m0 + sx) * lda + (k0) + sc * 8;   \
        const __half* bSrc = Bb + (long long)(n0 + sx) * ldb + (k0) + sc * 8;   \
        _Pragma("unroll")                                                       \
        for (int it = 0; it < 8; it++) {                                        \
            CP16(aD + it * (16 * SKB), aSrc + (long long)(it * 16) * lda);      \
            CP16(bD + it * (16 * SKB), bSrc + (long long)(it * 16) * ldb);      \
        }                                                                       \
    } while (0)

    STAGE(0, 0);
    CPC();

    // per-lane ldmatrix offsets: lanes 0-15 -> rows (x&15) @ +0B, 16-31 -> @ +16B
    const uint32_t aOff = (uint32_t)((wm + (lane & 15)) * SKB + (lane >> 4) * 16);
    const uint32_t bOff = (uint32_t)((wn + (lane & 15)) * SKB + (lane >> 4) * 16);

    for (int kb = 0; kb < NKB; kb++) {
        const int cur = kb & 1;
        if (kb + 1 < NKB) {
            STAGE(cur ^ 1, (kb + 1) << 6);
            CPC();
            CPW1();
        } else {
            CPW0();
        }
        __syncthreads();

        const uint32_t aT = base + cur * TILE_B + aOff;
        const uint32_t bT = base + (2 + cur) * TILE_B + bOff;
#pragma unroll
        for (int ks = 0; ks < 4; ks++) {
            uint32_t af[4][4], bq[4][4];
#pragma unroll
            for (int mi = 0; mi < 4; mi++)
                LDMX4(af[mi], aT + mi * (16 * SKB) + ks * 32);
#pragma unroll
            for (int ni = 0; ni < 4; ni++)
                LDMX4(bq[ni], bT + ni * (16 * SKB) + ks * 32);
#pragma unroll
            for (int mi = 0; mi < 4; mi++)
#pragma unroll
                for (int ni = 0; ni < 4; ni++) {
                    mma16816(acc[mi][2 * ni],     af[mi], bq[ni][0], bq[ni][2]);
                    mma16816(acc[mi][2 * ni + 1], af[mi], bq[ni][1], bq[ni][3]);
                }
        }
        __syncthreads();
    }
#undef STAGE

    // ---- epilogue ----
    const float* resb = (EPI >= 3) ? (res + (long long)bz * sR) : nullptr;
    float ls = 0.f, lq = 0.f;

#pragma unroll
    for (int mi = 0; mi < 4; mi++) {
        const int m = m0 + wm + mi * 16 + qr;
#pragma unroll
        for (int ni = 0; ni < 8; ni++) {
            const int nc = n0 + wn + ni * 8 + 2 * qc;
            float c0 = acc[mi][ni][0], c1 = acc[mi][ni][1];
            float c2 = acc[mi][ni][2], c3 = acc[mi][ni][3];
            if (EPI == 1 || EPI == 2 || EPI == 4) {
                const float bx = bias[nc], by = bias[nc + 1];
                c0 += bx; c1 += by; c2 += bx; c3 += by;
            }
            if (EPI == 2) {
                c0 = fmaxf(c0, 0.f); c1 = fmaxf(c1, 0.f);
                c2 = fmaxf(c2, 0.f); c3 = fmaxf(c3, 0.f);
            }
            if (EPI == 3) {
                // residual stored [N, M] (x^T layout, ld = SS)
                c0 += resb[(long long)nc * SS + m];
                c1 += resb[(long long)(nc + 1) * SS + m];
                c2 += resb[(long long)nc * SS + m + 8];
                c3 += resb[(long long)(nc + 1) * SS + m + 8];
            }
            if (EPI == 4) {
                // residual stored [M, N] (ld = DD)
                const float2 r0 = *(const float2*)(resb + (long long)m * DD + nc);
                const float2 r1 = *(const float2*)(resb + (long long)(m + 8) * DD + nc);
                c0 += r0.x; c1 += r0.y; c2 += r1.x; c3 += r1.y;
            }
            if (EPI >= 3) {
                ls += c0 + c1 + c2 + c3;
                lq += c0 * c0 + c1 * c1 + c2 * c2 + c3 * c3;
            }
            if (OUT == 0) {
                float* C = (float*)Cv + (long long)bz * sC;
                float2 lo; lo.x = c0; lo.y = c1;
                float2 hi; hi.x = c2; hi.y = c3;
                *(float2*)(C + (long long)m * ldc + nc) = lo;
                *(float2*)(C + (long long)(m + 8) * ldc + nc) = hi;
            } else if (OUT == 1) {
                __half* C = (__half*)Cv + (long long)bz * sC;
                *(__half2*)(C + (long long)m * ldc + nc) = __floats2half2_rn(c0, c1);
                *(__half2*)(C + (long long)(m + 8) * ldc + nc) = __floats2half2_rn(c2, c3);
            } else {
                __half* C = (__half*)Cv + (long long)bz * sC;
                C[(long long)nc * ldc + m]           = __float2half_rn(c0);
                C[(long long)(nc + 1) * ldc + m]     = __float2half_rn(c1);
                C[(long long)nc * ldc + m + 8]       = __float2half_rn(c2);
                C[(long long)(nc + 1) * ldc + m + 8] = __float2half_rn(c3);
            }
        }
    }

    if (EPI >= 3) {
        // block-reduce ls/lq into per-batch stats (reuse GEMM smem; mainloop done)
        float* sa = (float*)smem;
        float* sb = sa + 128;
        sa[tid] = ls; sb[tid] = lq;
        __syncthreads();
        for (int o = 64; o > 0; o >>= 1) {
            if (tid < o) { sa[tid] += sa[tid + o]; sb[tid] += sb[tid + o]; }
            __syncthreads();
        }
        if (tid == 0) {
            atomicAdd(stats + 2 * bz + 0, (double)sa[0]);
            atomicAdd(stats + 2 * bz + 1, (double)sb[0]);
        }
    }
}

// ---------------- transpose + fp32->fp16 convert: src[R,C] -> dst[C,R] ----------------
__global__ void transpose_h(const float* __restrict__ src, __half* __restrict__ dst,
                            int R, int C)
{
    const int b = blockIdx.z;
    src += (long long)b * R * C;
    dst += (long long)b * R * C;
    const int r0 = blockIdx.y * 32;
    const int c0 = blockIdx.x * 32;
    __shared__ float t[32][33];
    const int tx = threadIdx.x, ty = threadIdx.y;   // 32 x 8
#pragma unroll
    for (int i = 0; i < 32; i += 8)
        t[ty + i][tx] = src[(long long)(r0 + ty + i) * C + c0 + tx];
    __syncthreads();
#pragma unroll
    for (int i = 0; i < 32; i += 8)
        dst[(long long)(c0 + ty + i) * R + r0 + tx] = __float2half_rn(t[tx][ty + i]);
}

// ---------------- straight fp32->fp16 convert ----------------
__global__ void convert_h(const float* __restrict__ src, __half* __restrict__ dst)
{
    const long long i = (long long)blockIdx.x * 256 + threadIdx.x;
    const float4 v = ((const float4*)src)[i];
    __half2* d = (__half2*)dst + i * 2;
    d[0] = __floats2half2_rn(v.x, v.y);
    d[1] = __floats2half2_rn(v.z, v.w);
}

// ---------------- softmax on fp16 scores (in place, scaled) ----------------
__global__ void softmax_h(__half* __restrict__ sh, float scale)
{
    const long long row = blockIdx.x;
    uint4* p = (uint4*)(sh + row * SS);       // 512 uint4 per row (8 halves each)
    const int tid = threadIdx.x;              // 256 threads, 2 uint4 each
    __shared__ float red[256];

    uint4 u[2];
    float f[16];
    u[0] = p[tid];
    u[1] = p[tid + 256];
#pragma unroll
    for (int ii = 0; ii < 2; ii++) {
        const uint32_t* w = (const uint32_t*)&u[ii];
#pragma unroll
        for (int j = 0; j < 4; j++) {
            float2 d = __half22float2(*(const __half2*)&w[j]);
            f[ii * 8 + j * 2]     = d.x;
            f[ii * 8 + j * 2 + 1] = d.y;
        }
    }
    float mx = -INFINITY;
#pragma unroll
    for (int i = 0; i < 16; i++) mx = fmaxf(mx, f[i]);
    red[tid] = mx; __syncthreads();
    for (int o = 128; o > 0; o >>= 1) {
        if (tid < o) red[tid] = fmaxf(red[tid], red[tid + o]);
        __syncthreads();
    }
    mx = red[0];
    __syncthreads();

    float sum = 0.f;
#pragma unroll
    for (int i = 0; i < 16; i++) {
        f[i] = __expf((f[i] - mx) * scale);
        sum += f[i];
    }
    red[tid] = sum; __syncthreads();
    for (int o = 128; o > 0; o >>= 1) {
        if (tid < o) red[tid] += red[tid + o];
        __syncthreads();
    }
    const float inv = 1.f / red[0];
#pragma unroll
    for (int ii = 0; ii < 2; ii++) {
        uint32_t* w = (uint32_t*)&u[ii];
#pragma unroll
        for (int j = 0; j < 4; j++) {
            __half2 h = __floats2half2_rn(f[ii * 8 + j * 2] * inv,
                                          f[ii * 8 + j * 2 + 1] * inv);
            w[j] = *(const uint32_t*)&h;
        }
    }
    p[tid]       = u[0];
    p[tid + 256] = u[1];
}

__global__ void zero_acc_kernel()
{
    if (threadIdx.x < 32) g_acc[threadIdx.x] = 0.0;
}

// normalize y in place (fp32) + write fp16 copy
__global__ void apply1_kernel(float* __restrict__ y, __half* __restrict__ yh)
{
    const int b = blockIdx.y;
    const double sum = g_acc[2 * b], sq = g_acc[2 * b + 1];
    const double NE = (double)SS * DD;
    const double mean = sum / NE;
    double var = sq - NE * mean * mean;
    if (var < 0.0) var = 0.0;
    const float inv = (float)(1.0 / (sqrt(var) + 1e-7));
    const float fm = (float)mean;

    float4* y4 = ((float4*)y) + (long long)b * (SS * DD / 4);
    __half2* yh2 = ((__half2*)yh) + (long long)b * (SS * DD / 2);
    const long long i = (long long)blockIdx.x * 256 + threadIdx.x;  // grid.x = 2048
    float4 vv = y4[i];
    vv.x = (vv.x - fm) * inv; vv.y = (vv.y - fm) * inv;
    vv.z = (vv.z - fm) * inv; vv.w = (vv.w - fm) * inv;
    y4[i] = vv;
    yh2[i * 2]     = __floats2half2_rn(vv.x, vv.y);
    yh2[i * 2 + 1] = __floats2half2_rn(vv.z, vv.w);
}

// out[b,d,s] = (y2[b,s,d] - mean) * inv
__global__ void apply2t_kernel(const float* __restrict__ y2, float* __restrict__ out)
{
    const int b = blockIdx.z;
    const double sum = g_acc[16 + 2 * b], sq = g_acc[16 + 2 * b + 1];
    const double NE = (double)SS * DD;
    const double mean = sum / NE;
    double var = sq - NE * mean * mean;
    if (var < 0.0) var = 0.0;
    const float inv = (float)(1.0 / (sqrt(var) + 1e-7));
    const float fm = (float)mean;

    const int s0 = blockIdx.x * 32;
    const int d0 = blockIdx.y * 32;
    __shared__ float ys[32][33];
    const int tx = threadIdx.x, ty = threadIdx.y;

#pragma unroll
    for (int i = 0; i < 32; i += 8)
        ys[ty + i][tx] = y2[((long long)b * SS + s0 + ty + i) * DD + d0 + tx];
    __syncthreads();
#pragma unroll
    for (int i = 0; i < 32; i += 8)
        out[((long long)b * DD + d0 + ty + i) * SS + s0 + tx] =
            (ys[tx][ty + i] - fm) * inv;
}

// ---------------- host-side orchestration ----------------
template <typename T>
static T* sym(const void* symbol)
{
    void* p = nullptr;
    cudaGetSymbolAddress(&p, symbol);
    return (T*)p;
}

extern "C" void kernel_launch(void* const* d_in, const int* in_sizes, int n_in,
                              void* d_out, int out_size)
{
    const float* x  = (const float*)d_in[0];
    const float* Wq = (const float*)d_in[1];
    const float* Wk = (const float*)d_in[2];
    const float* Wv = (const float*)d_in[3];
    const float* Wo = (const float*)d_in[4];
    const float* W1 = (const float*)d_in[5];
    const float* b1 = (const float*)d_in[6];
    const float* W2 = (const float*)d_in[7];
    const float* b2 = (const float*)d_in[8];
    float* out = (float*)d_out;

    float*  py    = sym<float>((const void*)g_y);
    float*  ph2   = sym<float>((const void*)g_h2);
    double* pacc  = sym<double>((const void*)g_acc);
    __half* pxh   = sym<__half>((const void*)g_xh);
    __half* pqh   = sym<__half>((const void*)g_qh);
    __half* pkh   = sym<__half>((const void*)g_kh);
    __half* pvt   = sym<__half>((const void*)g_vt);
    __half* psh   = sym<__half>((const void*)g_sh);
    __half* pyh   = sym<__half>((const void*)g_yh);
    __half* ph1h  = sym<__half>((const void*)g_h1h);
    __half* pwqT  = sym<__half>((const void*)g_wqT);
    __half* pwkT  = sym<__half>((const void*)g_wkT);
    __half* pwvh  = sym<__half>((const void*)g_wvh);
    __half* pwoT  = sym<__half>((const void*)g_woT);
    __half* pwvoT = sym<__half>((const void*)g_wvoT);
    __half* pw1T  = sym<__half>((const void*)g_w1T);
    __half* pw2T  = sym<__half>((const void*)g_w2T);

    const long long sSD = (long long)SS * DD;
    const long long sSS = (long long)SS * SS;
    const long long sSF = (long long)SS * FF;
    const long long sDS = (long long)DD * SS;

    cudaFuncSetAttribute(gemm_h<0, 1>, cudaFuncAttributeMaxDynamicSharedMemorySize, SMEMB);
    cudaFuncSetAttribute(gemm_h<0, 2>, cudaFuncAttributeMaxDynamicSharedMemorySize, SMEMB);
    cudaFuncSetAttribute(gemm_h<2, 1>, cudaFuncAttributeMaxDynamicSharedMemorySize, SMEMB);
    cudaFuncSetAttribute(gemm_h<3, 0>, cudaFuncAttributeMaxDynamicSharedMemorySize, SMEMB);
    cudaFuncSetAttribute(gemm_h<4, 0>, cudaFuncAttributeMaxDynamicSharedMemorySize, SMEMB);

    zero_acc_kernel<<<1, 32>>>();

    // pre-pass: fp16 operands
    dim3 tblk(32, 8);
    transpose_h<<<dim3(SS / 32, DD / 32, BB), tblk>>>(x,  pxh,  DD, SS); // x[b]:[D,S]->[S,D]
    transpose_h<<<dim3(DD / 32, DD / 32, 1), tblk>>>(Wq, pwqT, DD, DD);
    transpose_h<<<dim3(DD / 32, DD / 32, 1), tblk>>>(Wk, pwkT, DD, DD);
    transpose_h<<<dim3(DD / 32, DD / 32, 1), tblk>>>(Wo, pwoT, DD, DD);
    convert_h<<<DD * DD / 1024, 256>>>(Wv, pwvh);                        // Wv fp16 (no transpose)
    transpose_h<<<dim3(FF / 32, DD / 32, 1), tblk>>>(W1, pw1T, DD, FF); // [D,F]->[F,D]
    transpose_h<<<dim3(DD / 32, FF / 32, 1), tblk>>>(W2, pw2T, FF, DD); // [F,D]->[D,F]

    dim3 blk(128);
    dim3 gW(DD / 128, DD / 128, 1);         // (4,4,1) weight-product GEMM
    dim3 gNarrow(DD / 128, SS / 128, BB);   // (4,32,8)
    dim3 gScore(SS / 128, SS / 128, BB);    // (32,32,8)
    dim3 gFFN(FF / 128, SS / 128, BB);      // (16,32,8)

    // W_voT[m,n] = sum_k WoT[m,k] * Wv[n,k]  ( = (Wv@Wo)^T )
    gemm_h<0, 1><<<gW, blk, SMEMB>>>(pwoT, pwvh, nullptr, pwvoT,
        DD, DD, DD, DD, 0, 0, 0, nullptr, 0, nullptr);

    // q,k = xh @ WT  (fp16 out)
    gemm_h<0, 1><<<gNarrow, blk, SMEMB>>>(pxh, pwqT, nullptr, pqh,
        DD, DD, DD, DD, sSD, 0, sSD, nullptr, 0, nullptr);
    gemm_h<0, 1><<<gNarrow, blk, SMEMB>>>(pxh, pwkT, nullptr, pkh,
        DD, DD, DD, DD, sSD, 0, sSD, nullptr, 0, nullptr);
    // v' = xh @ (WvWo)^T (fp16 out, transposed to [D,S])
    gemm_h<0, 2><<<gNarrow, blk, SMEMB>>>(pxh, pwvoT, nullptr, pvt,
        DD, DD, DD, SS, sSD, 0, sDS, nullptr, 0, nullptr);

    // scores = q @ k^T (fp16 out, in place softmax next)
    gemm_h<0, 1><<<gScore, blk, SMEMB>>>(pqh, pkh, nullptr, psh,
        DD, DD, DD, SS, sSD, sSD, sSS, nullptr, 0, nullptr);

    softmax_h<<<BB * SS, 256>>>(psh, 0.04419417382415922f /* 1/sqrt(512) */);

    // y = attn @ v' + x^T  (fused residual + stats stage 0, fp32 out)
    gemm_h<3, 0><<<gNarrow, blk, SMEMB>>>(psh, pvt, nullptr, py,
        SS, SS, SS, DD, sSS, sDS, sSD, x, sDS, pacc);

    apply1_kernel<<<dim3(2048, BB), 256>>>(py, pyh);

    // FFN
    gemm_h<2, 1><<<gFFN, blk, SMEMB>>>(pyh, pw1T, b1, ph1h,
        DD, DD, DD, FF, sSD, 0, sSF, nullptr, 0, nullptr);
    // h2 = h1 @ W2 + b2 + y  (fused residual + stats stage 1, fp32 out)
    gemm_h<4, 0><<<gNarrow, blk, SMEMB>>>(ph1h, pw2T, b2, ph2,
        FF, FF, FF, DD, sSF, 0, sSD, py, sSD, pacc + 16);

    apply2t_kernel<<<dim3(SS / 32, DD / 32, BB), tblk>>>(ph2, out);

    (void)in_sizes; (void)n_in; (void)out_size;
}